// round 11
// baseline (speedup 1.0000x reference)
#include <cuda_runtime.h>
#include <cuda_bf16.h>
#include <math.h>

#define N_Uc 30000
#define N_Ic 15000
#define NNc  45000
#define Dc   64
#define NNZc 480000
#define BQ   2048
#define NQ   (2*BQ)
#define JT_U 12
#define JT_I 6
#define PSTR 16
#define CHUNK 2500
#define NTILES 40
#define NB_SCAN 59
#define NB_U 3750
#define NB_I 1875
#define INV_TEMP 5.0f
#define LSE_SHIFT 40.0f
#define NEG_SLOPE_C 0.2f
#define LOG_EPS_C (-18.420680743952367f)
#define FULLMASK 0xffffffffu
#define NEGINF (-INFINITY)

typedef unsigned long long ull;
typedef unsigned int uint;
typedef unsigned short ushort;

// ---------------- scratch ----------------
__device__ float g_EuA[N_Uc*Dc], g_EuB[N_Uc*Dc];
__device__ float g_EiA[N_Ic*Dc], g_EiB[N_Ic*Dc];
__device__ float g_sEu[N_Uc*Dc], g_sEi[N_Ic*Dc];
__device__ float g_sGu[N_Uc*Dc], g_sGi[N_Ic*Dc];
__device__ float g_feat[NNc*Dc];
__device__ float g_el[NNc*4], g_er[NNc*4];
__device__ int   g_ioff[N_Ic+1];
__device__ int   g_icur[N_Ic];
__device__ int   g_ilist[NNZc];
__device__ int   g_bsum[64];
__device__ float g_pm[NQ*PSTR], g_ps[NQ*PSTR];
__device__ float g_acc[8];
__device__ ushort g_Ehi[NNc*Dc], g_Elo[NNc*Dc];
__device__ ushort g_Qhi[NQ*Dc],  g_Qlo[NQ*Dc];

// ---------------- helpers ----------------
__device__ __forceinline__ float warpSum(float v){
    #pragma unroll
    for (int o=16;o;o>>=1) v += __shfl_xor_sync(FULLMASK, v, o);
    return v;
}
__device__ __forceinline__ int warpSumI(int v){
    #pragma unroll
    for (int o=16;o;o>>=1) v += __shfl_xor_sync(FULLMASK, v, o);
    return v;
}
__device__ __forceinline__ float leakyf(float x){ return x > 0.f ? x : NEG_SLOPE_C*x; }
__device__ __forceinline__ float eluf(float x){ return x > 0.f ? x : expm1f(x); }

struct F4 { float x,y,z,w; };
__device__ __forceinline__ F4 ldf4(const float* p){ float4 v = *(const float4*)p; return {v.x,v.y,v.z,v.w}; }
__device__ __forceinline__ F4 leaky4(F4 a){ return { leakyf(a.x), leakyf(a.y), leakyf(a.z), leakyf(a.w) }; }
__device__ __forceinline__ F4 add4(F4 a, F4 b){ return { a.x+b.x, a.y+b.y, a.z+b.z, a.w+b.w }; }
__device__ __forceinline__ F4 exp4(F4 a){ return { __expf(a.x), __expf(a.y), __expf(a.z), __expf(a.w) }; }
__device__ __forceinline__ F4 warpSum4(F4 v){
    v.x = warpSum(v.x); v.y = warpSum(v.y); v.z = warpSum(v.z); v.w = warpSum(v.w);
    return v;
}
__device__ __forceinline__ float comp4(F4 v, int h){
    return h==0 ? v.x : (h==1 ? v.y : (h==2 ? v.z : v.w));
}
__device__ __forceinline__ unsigned smem_u32(const void* p){
    return (unsigned)__cvta_generic_to_shared(p);
}
__device__ __forceinline__ uint pack_hi2(float a, float b){
    __nv_bfloat16 h0 = __float2bfloat16_rn(a);
    __nv_bfloat16 h1 = __float2bfloat16_rn(b);
    return (uint)__bfloat16_as_ushort(h0) | ((uint)__bfloat16_as_ushort(h1) << 16);
}
__device__ __forceinline__ uint pack_lo2(float a, float b){
    __nv_bfloat16 h0 = __float2bfloat16_rn(a);
    __nv_bfloat16 h1 = __float2bfloat16_rn(b);
    __nv_bfloat16 l0 = __float2bfloat16_rn(a - __bfloat162float(h0));
    __nv_bfloat16 l1 = __float2bfloat16_rn(b - __bfloat162float(h1));
    return (uint)__bfloat16_as_ushort(l0) | ((uint)__bfloat16_as_ushort(l1) << 16);
}

#define LDSM4(r0,r1,r2,r3,addr) \
    asm volatile("ldmatrix.sync.aligned.m8n8.x4.shared.b16 {%0,%1,%2,%3}, [%4];" \
        : "=r"(r0),"=r"(r1),"=r"(r2),"=r"(r3) : "r"(addr))

#define MMA16816(c,a0,a1,a2,a3,b0,b1) \
    asm volatile("mma.sync.aligned.m16n8k16.row.col.f32.bf16.bf16.f32 " \
        "{%0,%1,%2,%3}, {%4,%5,%6,%7}, {%8,%9}, {%0,%1,%2,%3};" \
        : "+f"(c[0]),"+f"(c[1]),"+f"(c[2]),"+f"(c[3]) \
        : "r"(a0),"r"(a1),"r"(a2),"r"(a3), "r"(b0),"r"(b1))

// ---------------- setup ----------------
__global__ __launch_bounds__(256) void k_init(const float* __restrict__ E0u, const float* __restrict__ E0i){
    const int TOT = N_Uc*Dc + N_Ic*Dc;
    int gid = blockIdx.x*256 + threadIdx.x;
    if (gid <= N_Ic) g_ioff[gid] = 0;
    if (gid < 8)     g_acc[gid]  = 0.f;
    float loc = 0.f;
    for (int i = gid; i < TOT; i += gridDim.x*256){
        float v;
        if (i < N_Uc*Dc){ v = E0u[i]; g_EuA[i]=v; g_sEu[i]=v; g_sGu[i]=v; }
        else            { int j=i-N_Uc*Dc; v = E0i[j]; g_EiA[j]=v; g_sEi[j]=v; g_sGi[j]=v; }
        loc += v*v;
    }
    loc = warpSum(loc);
    __shared__ float sw[8];
    int lane = threadIdx.x & 31, wid = threadIdx.x >> 5;
    if (lane==0) sw[wid]=loc;
    __syncthreads();
    if (wid==0){
        float v = lane<8 ? sw[lane] : 0.f;
        v = warpSum(v);
        if (lane==0) atomicAdd(&g_acc[0], v);
    }
}

__global__ __launch_bounds__(256) void k_count(const int* __restrict__ i_idx){
    int j = blockIdx.x*256 + threadIdx.x;
    if (j < NNZc) atomicAdd(&g_ioff[i_idx[j]], 1);
}

__global__ __launch_bounds__(256) void k_scanA(){
    int b = blockIdx.x;
    int i = b*256 + threadIdx.x;
    int cnt = (i < N_Ic) ? g_ioff[i] : 0;
    int lane = threadIdx.x & 31, w = threadIdx.x >> 5;
    int x = cnt;
    #pragma unroll
    for (int o=1;o<32;o<<=1){
        int y = __shfl_up_sync(FULLMASK, x, o);
        if (lane >= o) x += y;
    }
    __shared__ int ws[8];
    if (lane==31) ws[w] = x;
    __syncthreads();
    if (w==0){
        int v = lane<8 ? ws[lane] : 0;
        #pragma unroll
        for (int o=1;o<8;o<<=1){
            int y = __shfl_up_sync(FULLMASK, v, o);
            if (lane >= o) v += y;
        }
        if (lane<8) ws[lane] = v;
    }
    __syncthreads();
    int excl = x - cnt + (w>0 ? ws[w-1] : 0);
    if (i < N_Ic) g_ioff[i] = excl;
    if (threadIdx.x == 255) g_bsum[b] = excl + cnt;
}

__global__ __launch_bounds__(256) void k_scanC(){
    __shared__ int spref;
    int b = blockIdx.x;
    if (threadIdx.x < 32){
        int l = threadIdx.x;
        int i0 = 2*l, i1 = 2*l+1;
        int v0 = (i0 < NB_SCAN && i0 < b) ? g_bsum[i0] : 0;
        int v1 = (i1 < NB_SCAN && i1 < b) ? g_bsum[i1] : 0;
        int s = warpSumI(v0 + v1);
        if (l==0) spref = s;
    }
    __syncthreads();
    int i = b*256 + threadIdx.x;
    if (i < N_Ic){
        int v = g_ioff[i] + spref;
        g_ioff[i] = v; g_icur[i] = v;
    }
    if (i == 0) g_ioff[N_Ic] = NNZc;
}

__global__ __launch_bounds__(256) void k_fill(const int* __restrict__ i_idx){
    int j = blockIdx.x*256 + threadIdx.x;
    if (j < NNZc){
        int p = atomicAdd(&g_icur[i_idx[j]], 1);
        g_ilist[p] = j;
    }
}

// ---------------- per-layer ----------------
__global__ __launch_bounds__(256) void k_feat(int flip, const float* __restrict__ W,
                                              const float* __restrict__ al, const float* __restrict__ ar){
    __shared__ float sW[64*64];
    __shared__ float sh[16*64];
    int tid = threadIdx.x;
    const float* Eu = flip ? g_EuB : g_EuA;
    const float* Ei = flip ? g_EiB : g_EiA;
    int r0 = blockIdx.x*16;
    for (int i=tid;i<4096;i+=256) sW[i]=W[i];
    for (int i=tid;i<1024;i+=256){
        int node = r0 + (i>>6); int k = i&63;
        float v = 0.f;
        if (node < NNc) v = node < N_Uc ? Eu[node*64+k] : Ei[(node-N_Uc)*64+k];
        sh[i] = v;
    }
    __syncthreads();
    int r = tid>>6, c = tid&63;
    float acc[4] = {0.f,0.f,0.f,0.f};
    #pragma unroll
    for (int k=0;k<64;k++){
        float wv = sW[k*64+c];
        acc[0] += sh[ r     *64+k]*wv;
        acc[1] += sh[(r+4 ) *64+k]*wv;
        acc[2] += sh[(r+8 ) *64+k]*wv;
        acc[3] += sh[(r+12)*64+k]*wv;
    }
    float alc = al[c], arc = ar[c];
    #pragma unroll
    for (int rr=0; rr<4; rr++){
        int node = r0 + r + rr*4;
        if (node < NNc){
            float a = acc[rr];
            g_feat[node*64+c] = a;
            float vl = a*alc, vr = a*arc;
            #pragma unroll
            for (int o=8;o;o>>=1){
                vl += __shfl_down_sync(FULLMASK, vl, o, 16);
                vr += __shfl_down_sync(FULLMASK, vr, o, 16);
            }
            if ((c&15)==0){ g_el[node*4+(c>>4)] = vl; g_er[node*4+(c>>4)] = vr; }
        }
    }
}

// fused user+item GAT/LightGCN kernel; doSplit=1 (layer 1) also emits bf16 hi/lo of final sE
__global__ __launch_bounds__(256) void k_ui(int flip, int doSplit, const float* __restrict__ vals,
                                            const int* __restrict__ i_idx){
    __shared__ int    s_u[8][32];
    __shared__ float4 s_a4[8][32];
    __shared__ float  s_v[8][32];
    int lane = threadIdx.x & 31;
    int w = threadIdx.x >> 5;
    const float* Eu = flip ? g_EuB : g_EuA;
    const float* Ei = flip ? g_EiB : g_EiA;
    int h = lane >> 3;

    if (blockIdx.x < NB_U){
        int u = blockIdx.x*8 + w;
        float* EuN = flip ? g_EuA : g_EuB;
        F4 er4 = ldf4(g_er + u*4);
        int src = u;
        if (lane < 16){ src = N_Uc + i_idx[u*16 + lane]; s_v[w][lane] = vals[u*16 + lane]; }
        bool valid = lane < 17;
        F4 a4 = { 0.f,0.f,0.f,0.f };
        if (valid){
            F4 e4 = leaky4(add4(ldf4(g_el + src*4), er4));
            a4 = exp4(e4);
        }
        F4 s4 = warpSum4(a4);
        if (valid){ s_u[w][lane]=src; s_a4[w][lane]=make_float4(a4.x,a4.y,a4.z,a4.w); }
        __syncwarp();
        float g0=0.f, g1=0.f, z0=0.f, z1=0.f;
        #pragma unroll
        for (int k=0;k<16;k++){
            int sk = s_u[w][k];
            float a = ((const float*)&s_a4[w][k])[h];
            float vv = s_v[w][k];
            float2 f2 = ((const float2*)(g_feat + sk*64))[lane];
            float2 i2 = ((const float2*)(Ei + (sk-N_Uc)*64))[lane];
            g0 += a*f2.x;  g1 += a*f2.y;
            z0 += vv*i2.x; z1 += vv*i2.y;
        }
        {
            float a = ((const float*)&s_a4[w][16])[h];
            float2 f2 = ((const float2*)(g_feat + u*64))[lane];
            g0 += a*f2.x; g1 += a*f2.y;
        }
        float sh = comp4(s4, h);
        float2* sg = (float2*)(g_sGu + u*64);
        float2 cg = sg[lane]; cg.x += eluf(g0/sh); cg.y += eluf(g1/sh); sg[lane] = cg;
        float2 eu = ((const float2*)(Eu + u*64))[lane];
        float2 e; e.x = eu.x + z0; e.y = eu.y + z1;
        ((float2*)(EuN + u*64))[lane] = e;
        float2* se = (float2*)(g_sEu + u*64);
        float2 cs = se[lane]; cs.x += e.x; cs.y += e.y; se[lane] = cs;
        if (doSplit){
            ((uint*)(g_Ehi + u*64))[lane] = pack_hi2(cs.x, cs.y);
            ((uint*)(g_Elo + u*64))[lane] = pack_lo2(cs.x, cs.y);
        }
    } else {
        int i = (blockIdx.x - NB_U)*8 + w;
        if (i >= N_Ic) return;
        int node = N_Uc + i;
        float* EiN = flip ? g_EiA : g_EiB;
        int off = g_ioff[i];
        int cnt = g_ioff[i+1] - off;
        int deg = cnt + 1;
        F4 er4 = ldf4(g_er + node*4);
        float g0=0.f, g1=0.f, z0=0.f, z1=0.f;
        F4 ssum = {0.f,0.f,0.f,0.f};
        for (int base=0; base<deg; base+=32){
            int k = base + lane;
            if (k < deg){
                int src; float vv;
                if (k < cnt){
                    int j = g_ilist[off+k];
                    src = j >> 4; vv = vals[j];
                } else { src = node; vv = 0.f; }
                F4 e4 = leaky4(add4(ldf4(g_el + src*4), er4));
                F4 a4 = exp4(e4);
                ssum = add4(ssum, a4);
                s_u[w][lane] = src;
                s_a4[w][lane] = make_float4(a4.x, a4.y, a4.z, a4.w);
                s_v[w][lane] = vv;
            }
            __syncwarp();
            int kmax = min(32, deg - base);
            for (int kk=0; kk<kmax; kk++){
                int sk = s_u[w][kk];
                float a = ((const float*)&s_a4[w][kk])[h];
                float2 f2 = ((const float2*)(g_feat + sk*64))[lane];
                g0 += a*f2.x; g1 += a*f2.y;
                if (sk < N_Uc){
                    float vv = s_v[w][kk];
                    float2 u2 = ((const float2*)(Eu + sk*64))[lane];
                    z0 += vv*u2.x; z1 += vv*u2.y;
                }
            }
            __syncwarp();
        }
        F4 s4 = warpSum4(ssum);
        float sh = comp4(s4, h);
        float2* sg = (float2*)(g_sGi + i*64);
        float2 cg = sg[lane]; cg.x += eluf(g0/sh); cg.y += eluf(g1/sh); sg[lane] = cg;
        float2 ei = ((const float2*)(Ei + i*64))[lane];
        float2 e; e.x = ei.x + z0; e.y = ei.y + z1;
        ((float2*)(EiN + i*64))[lane] = e;
        float2* se = (float2*)(g_sEi + i*64);
        float2 cs = se[lane]; cs.x += e.x; cs.y += e.y; se[lane] = cs;
        if (doSplit){
            ((uint*)(g_Ehi + node*64))[lane] = pack_hi2(cs.x, cs.y);
            ((uint*)(g_Elo + node*64))[lane] = pack_lo2(cs.x, cs.y);
        }
    }
}

// ---------------- bf16 split (queries only; E fused into k_ui layer 1) ----------------
__global__ __launch_bounds__(256) void k_splitQ(const int* __restrict__ uids, const int* __restrict__ iids){
    int t = blockIdx.x*256 + threadIdx.x;
    const int NQ4 = NQ*Dc/4;
    if (t >= NQ4) return;
    int idx = t*4;
    int q = idx >> 6, k = idx & 63;
    const float* src = ((q < BQ) ? (g_sGu + uids[q]*64) : (g_sGi + iids[q-BQ]*64)) + k;
    float4 v = *(const float4*)src;
    uint h0 = pack_hi2(v.x, v.y), h1 = pack_hi2(v.z, v.w);
    uint l0 = pack_lo2(v.x, v.y), l1 = pack_lo2(v.z, v.w);
    *(uint2*)(g_Qhi + idx) = make_uint2(h0, h1);
    *(uint2*)(g_Qlo + idx) = make_uint2(l0, l1);
}

// ---------------- loss: bf16 split MMA + fixed-shift LSE, double-buffered ----------------
__global__ __launch_bounds__(256,2) void k_mma(){
    __shared__ uint sEhi[2][2304];
    __shared__ uint sElo[2][2304];
    int bx = blockIdx.x;
    int tid = threadIdx.x;
    int lane = tid & 31, w = tid >> 5;
    int qt, split, qOff, eOff;
    if (bx < 16*JT_U){ qt = bx / JT_U; split = bx % JT_U; qOff = 0;    eOff = 0; }
    else { int b = bx - 16*JT_U; qt = b / JT_I; split = b % JT_I; qOff = BQ; eOff = N_Uc; }
    int rowBase = eOff + split*CHUNK;
    int rowEnd  = rowBase + CHUNK;

    int qrow = qOff + qt*128 + w*16 + (lane>>2);
    const uint* Qh = (const uint*)g_Qhi;
    const uint* Ql = (const uint*)g_Qlo;
    uint Ahi[4][4], Alo[4][4];
    #pragma unroll
    for (int ks=0; ks<4; ks++){
        int k2 = ks*8 + (lane&3);
        Ahi[ks][0] = Qh[ qrow   *32 + k2    ];
        Ahi[ks][1] = Qh[(qrow+8)*32 + k2    ];
        Ahi[ks][2] = Qh[ qrow   *32 + k2 + 4];
        Ahi[ks][3] = Qh[(qrow+8)*32 + k2 + 4];
        Alo[ks][0] = Ql[ qrow   *32 + k2    ];
        Alo[ks][1] = Ql[(qrow+8)*32 + k2    ];
        Alo[ks][2] = Ql[ qrow   *32 + k2 + 4];
        Alo[ks][3] = Ql[(qrow+8)*32 + k2 + 4];
    }

    int L8 = lane & 7, g = lane >> 3;
    int j_off = ((g & 2) << 2) + L8;
    int k_off2 = (g & 1) * 16;
    uint laneB = (uint)(j_off*144 + k_off2);
    uint baseHi[2] = { smem_u32(sEhi[0]) + laneB, smem_u32(sEhi[1]) + laneB };
    uint baseLo[2] = { smem_u32(sElo[0]) + laneB, smem_u32(sElo[1]) + laneB };

    int rr = tid >> 2, cc = tid & 3;
    const uint4* Eh4 = (const uint4*)g_Ehi;
    const uint4* El4 = (const uint4*)g_Elo;
    uint so = rr*36 + cc*8;
    uint4 rp0, rp1, rp2, rp3;
    // prefetch + stage tile 0 into buf 0
    {
        int jj = rowBase + rr;
        bool v = jj < rowEnd;
        long gi = (long)jj*8 + cc*2;
        rp0 = v ? Eh4[gi]   : make_uint4(0,0,0,0);
        rp1 = v ? Eh4[gi+1] : make_uint4(0,0,0,0);
        rp2 = v ? El4[gi]   : make_uint4(0,0,0,0);
        rp3 = v ? El4[gi+1] : make_uint4(0,0,0,0);
        *(uint4*)(sEhi[0] + so)     = rp0;
        *(uint4*)(sEhi[0] + so + 4) = rp1;
        *(uint4*)(sElo[0] + so)     = rp2;
        *(uint4*)(sElo[0] + so + 4) = rp3;
    }
    __syncthreads();

    float s0 = 0.f, s1 = 0.f;

    for (int jt=0; jt<NTILES; jt++){
        // prefetch next tile from gmem (latency hidden by MMAs below)
        if (jt+1 < NTILES){
            int jj = rowBase + (jt+1)*64 + rr;
            bool v = jj < rowEnd;
            long gi = (long)jj*8 + cc*2;
            rp0 = v ? Eh4[gi]   : make_uint4(0,0,0,0);
            rp1 = v ? Eh4[gi+1] : make_uint4(0,0,0,0);
            rp2 = v ? El4[gi]   : make_uint4(0,0,0,0);
            rp3 = v ? El4[gi+1] : make_uint4(0,0,0,0);
        }
        int buf = jt & 1;
        uint bHi = baseHi[buf], bLo = baseLo[buf];

        float acc[8][4];
        #pragma unroll
        for (int n=0;n<8;n++){ acc[n][0]=0.f; acc[n][1]=0.f; acc[n][2]=0.f; acc[n][3]=0.f; }

        #pragma unroll
        for (int ks=0; ks<4; ks++){
            uint kb = ks*32;
            #pragma unroll
            for (int p=0; p<4; p++){
                uint bh0,bh1,bh2,bh3, bl0,bl1,bl2,bl3;
                LDSM4(bh0,bh1,bh2,bh3, bHi + p*2304 + kb);
                LDSM4(bl0,bl1,bl2,bl3, bLo + p*2304 + kb);
                MMA16816(acc[2*p],   Ahi[ks][0],Ahi[ks][1],Ahi[ks][2],Ahi[ks][3], bh0,bh1);
                MMA16816(acc[2*p],   Alo[ks][0],Alo[ks][1],Alo[ks][2],Alo[ks][3], bh0,bh1);
                MMA16816(acc[2*p],   Ahi[ks][0],Ahi[ks][1],Ahi[ks][2],Ahi[ks][3], bl0,bl1);
                MMA16816(acc[2*p+1], Ahi[ks][0],Ahi[ks][1],Ahi[ks][2],Ahi[ks][3], bh2,bh3);
                MMA16816(acc[2*p+1], Alo[ks][0],Alo[ks][1],Alo[ks][2],Alo[ks][3], bh2,bh3);
                MMA16816(acc[2*p+1], Ahi[ks][0],Ahi[ks][1],Ahi[ks][2],Ahi[ks][3], bl2,bl3);
            }
        }

        // stage next tile into the other buffer (safe: other warps read buf, not buf^1)
        if (jt+1 < NTILES){
            int nb = buf ^ 1;
            *(uint4*)(sEhi[nb] + so)     = rp0;
            *(uint4*)(sEhi[nb] + so + 4) = rp1;
            *(uint4*)(sElo[nb] + so)     = rp2;
            *(uint4*)(sElo[nb] + so + 4) = rp3;
        }

        // fixed-shift epilogue
        int jl0 = jt*64 + 2*(lane&3);
        #pragma unroll
        for (int n=0;n<8;n++){
            float v0 = acc[n][0], v1 = acc[n][1], v2 = acc[n][2], v3 = acc[n][3];
            if (jt == NTILES-1){
                int jl = jl0 + n*8;
                if (jl   >= CHUNK){ v0 = NEGINF; v2 = NEGINF; }
                if (jl+1 >= CHUNK){ v1 = NEGINF; v3 = NEGINF; }
            }
            s0 += __expf(fmaf(v0, INV_TEMP, -LSE_SHIFT)) + __expf(fmaf(v1, INV_TEMP, -LSE_SHIFT));
            s1 += __expf(fmaf(v2, INV_TEMP, -LSE_SHIFT)) + __expf(fmaf(v3, INV_TEMP, -LSE_SHIFT));
        }
        __syncthreads();
    }

    #pragma unroll
    for (int o=1; o<4; o<<=1){
        s0 += __shfl_xor_sync(FULLMASK, s0, o);
        s1 += __shfl_xor_sync(FULLMASK, s1, o);
    }
    if ((lane & 3) == 0){
        int gq = qOff + qt*128 + w*16 + (lane>>2);
        g_pm[gq*PSTR + split] = LSE_SHIFT;
        g_ps[gq*PSTR + split] = s0;
        g_pm[(gq+8)*PSTR + split] = LSE_SHIFT;
        g_ps[(gq+8)*PSTR + split] = s1;
    }
}

__global__ __launch_bounds__(256) void k_finsc(const int* __restrict__ uids, const int* __restrict__ iids,
                                               const int* __restrict__ pos, const int* __restrict__ neg){
    if (blockIdx.x < 16){
        int q = blockIdx.x*256 + threadIdx.x;
        int T = (q < BQ) ? JT_U : JT_I;
        float M = NEGINF;
        for (int t=0;t<T;t++) M = fmaxf(M, g_pm[q*PSTR+t]);
        float S = 0.f;
        for (int t=0;t<T;t++) S += g_ps[q*PSTR+t]*expf(g_pm[q*PSTR+t]-M);
        float lse = M + logf(S);
        float dmax = fmaxf(lse, LOG_EPS_C);
        float dmin = fminf(lse, LOG_EPS_C);
        float v = dmax + log1pf(expf(dmin - dmax));
        v = warpSum(v);
        __shared__ float sw[8];
        int lane = threadIdx.x & 31, wid = threadIdx.x >> 5;
        if (lane==0) sw[wid]=v;
        __syncthreads();
        if (wid==0){
            float x = lane<8 ? sw[lane] : 0.f;
            x = warpSum(x);
            if (lane==0) atomicAdd(&g_acc[blockIdx.x < 8 ? 1 : 2], x);
        }
    } else {
        int q = (blockIdx.x-16)*8 + (threadIdx.x>>5);
        if (q >= BQ) return;
        int lane = threadIdx.x & 31;
        int u = uids[q], it = iids[q], p = pos[q], ng = neg[q];
        const float* Gu = g_sGu + u*64;
        const float* Eu = g_sEu + u*64;
        const float* Gi = g_sGi + it*64;
        const float* Eit = g_sEi + it*64;
        const float* Ep = g_sEi + p*64;
        const float* En = g_sEi + ng*64;
        float du=0.f, di=0.f, dd=0.f;
        #pragma unroll
        for (int t=0;t<2;t++){
            int rr = lane + 32*t;
            float eu = Eu[rr];
            du += Gu[rr]*eu;
            di += Gi[rr]*Eit[rr];
            dd += eu*(Ep[rr]-En[rr]);
        }
        du = warpSum(du); di = warpSum(di); dd = warpSum(dd);
        if (lane==0){
            atomicAdd(&g_acc[3], du);
            atomicAdd(&g_acc[4], di);
            float x = -dd;
            float sp = fmaxf(x,0.f) + log1pf(expf(-fabsf(x)));
            atomicAdd(&g_acc[5], sp);
        }
    }
}

__global__ void k_out(float* out){
    float Bf = (float)BQ;
    float neg_score = g_acc[1]/Bf + g_acc[2]/Bf;
    float pos_score = (g_acc[3] + g_acc[4]) * INV_TEMP / Bf;
    float loss_s = neg_score - pos_score;
    float loss_r = g_acc[5]/Bf;
    float reg = 1e-7f * g_acc[0];
    out[0] = loss_r + 0.2f*loss_s + reg;
    out[1] = loss_r;
    out[2] = 0.2f*loss_s;
}

// ---------------- launch ----------------
extern "C" void kernel_launch(void* const* d_in, const int* in_sizes, int n_in,
                              void* d_out, int out_size){
    const float* E_u_0    = (const float*)d_in[0];
    const float* E_i_0    = (const float*)d_in[1];
    const float* adj_vals = (const float*)d_in[2];
    const float* W        = (const float*)d_in[3];
    const float* attn_l   = (const float*)d_in[4];
    const float* attn_r   = (const float*)d_in[5];
    const int*   i_idx    = (const int*)d_in[7];
    const int*   uids     = (const int*)d_in[10];
    const int*   iids     = (const int*)d_in[11];
    const int*   pos      = (const int*)d_in[12];
    const int*   neg      = (const int*)d_in[13];
    float* out = (float*)d_out;

    k_init  <<<1024, 256>>>(E_u_0, E_i_0);                 // 0
    k_count <<<(NNZc+255)/256, 256>>>(i_idx);              // 1
    k_feat  <<<(NNc+15)/16, 256>>>(0, W, attn_l, attn_r);  // 2
    k_scanA <<<NB_SCAN, 256>>>();                          // 3
    k_scanC <<<NB_SCAN, 256>>>();                          // 4
    k_fill  <<<(NNZc+255)/256, 256>>>(i_idx);              // 5
    k_ui    <<<NB_U + NB_I, 256>>>(0, 0, adj_vals, i_idx); // 6
    k_feat  <<<(NNc+15)/16, 256>>>(1, W, attn_l, attn_r);  // 7
    k_ui    <<<NB_U + NB_I, 256>>>(1, 1, adj_vals, i_idx); // 8
    k_splitQ<<<(NQ*Dc/4 + 255)/256, 256>>>(uids, iids);    // 9
    k_mma   <<<16*JT_U + 16*JT_I, 256>>>();                // 10
    k_finsc <<<16 + BQ/8, 256>>>(uids, iids, pos, neg);    // 11
    k_out   <<<1, 1>>>(out);                               // 12
}

// round 12
// speedup vs baseline: 1.0239x; 1.0239x over previous
#include <cuda_runtime.h>
#include <cuda_bf16.h>
#include <math.h>

#define N_Uc 30000
#define N_Ic 15000
#define NNc  45000
#define Dc   64
#define NNZc 480000
#define BQ   2048
#define NQ   (2*BQ)
#define JT_U 12
#define JT_I 6
#define PSTR 16
#define CHUNK 2500
#define NTILES 40
#define NB_SCAN 59
#define NB_U 3750
#define NB_I 1875
#define INV_TEMP 5.0f
#define LSE_SHIFT 40.0f
#define NEG_SLOPE_C 0.2f
#define LOG_EPS_C (-18.420680743952367f)
#define FULLMASK 0xffffffffu
#define NEGINF (-INFINITY)

typedef unsigned long long ull;
typedef unsigned int uint;
typedef unsigned short ushort;

// ---------------- scratch ----------------
__device__ float g_EuA[N_Uc*Dc], g_EuB[N_Uc*Dc];
__device__ float g_EiA[N_Ic*Dc], g_EiB[N_Ic*Dc];
__device__ float g_sEu[N_Uc*Dc], g_sEi[N_Ic*Dc];
__device__ float g_sGu[N_Uc*Dc], g_sGi[N_Ic*Dc];
__device__ float g_feat[NNc*Dc];
__device__ float g_el[NNc*4], g_er[NNc*4];
__device__ int   g_ioff[N_Ic+1];
__device__ int   g_icur[N_Ic];
__device__ int   g_ilist[NNZc];
__device__ int   g_bsum[64];
__device__ float g_pm[NQ*PSTR], g_ps[NQ*PSTR];
__device__ float g_acc[8];
__device__ ushort g_Ehi[NNc*Dc], g_Elo[NNc*Dc];
__device__ ushort g_Qhi[NQ*Dc],  g_Qlo[NQ*Dc];

// ---------------- helpers ----------------
__device__ __forceinline__ float warpSum(float v){
    #pragma unroll
    for (int o=16;o;o>>=1) v += __shfl_xor_sync(FULLMASK, v, o);
    return v;
}
__device__ __forceinline__ int warpSumI(int v){
    #pragma unroll
    for (int o=16;o;o>>=1) v += __shfl_xor_sync(FULLMASK, v, o);
    return v;
}
__device__ __forceinline__ float leakyf(float x){ return x > 0.f ? x : NEG_SLOPE_C*x; }
__device__ __forceinline__ float eluf(float x){ return x > 0.f ? x : expm1f(x); }

struct F4 { float x,y,z,w; };
__device__ __forceinline__ F4 ldf4(const float* p){ float4 v = *(const float4*)p; return {v.x,v.y,v.z,v.w}; }
__device__ __forceinline__ F4 leaky4(F4 a){ return { leakyf(a.x), leakyf(a.y), leakyf(a.z), leakyf(a.w) }; }
__device__ __forceinline__ F4 add4(F4 a, F4 b){ return { a.x+b.x, a.y+b.y, a.z+b.z, a.w+b.w }; }
__device__ __forceinline__ F4 exp4(F4 a){ return { __expf(a.x), __expf(a.y), __expf(a.z), __expf(a.w) }; }
__device__ __forceinline__ F4 warpSum4(F4 v){
    v.x = warpSum(v.x); v.y = warpSum(v.y); v.z = warpSum(v.z); v.w = warpSum(v.w);
    return v;
}
__device__ __forceinline__ float comp4(F4 v, int h){
    return h==0 ? v.x : (h==1 ? v.y : (h==2 ? v.z : v.w));
}
__device__ __forceinline__ unsigned smem_u32(const void* p){
    return (unsigned)__cvta_generic_to_shared(p);
}
__device__ __forceinline__ uint pack_hi2(float a, float b){
    __nv_bfloat16 h0 = __float2bfloat16_rn(a);
    __nv_bfloat16 h1 = __float2bfloat16_rn(b);
    return (uint)__bfloat16_as_ushort(h0) | ((uint)__bfloat16_as_ushort(h1) << 16);
}
__device__ __forceinline__ uint pack_lo2(float a, float b){
    __nv_bfloat16 h0 = __float2bfloat16_rn(a);
    __nv_bfloat16 h1 = __float2bfloat16_rn(b);
    __nv_bfloat16 l0 = __float2bfloat16_rn(a - __bfloat162float(h0));
    __nv_bfloat16 l1 = __float2bfloat16_rn(b - __bfloat162float(h1));
    return (uint)__bfloat16_as_ushort(l0) | ((uint)__bfloat16_as_ushort(l1) << 16);
}

#define LDSM4(r0,r1,r2,r3,addr) \
    asm volatile("ldmatrix.sync.aligned.m8n8.x4.shared.b16 {%0,%1,%2,%3}, [%4];" \
        : "=r"(r0),"=r"(r1),"=r"(r2),"=r"(r3) : "r"(addr))

#define MMA16816(c,a0,a1,a2,a3,b0,b1) \
    asm volatile("mma.sync.aligned.m16n8k16.row.col.f32.bf16.bf16.f32 " \
        "{%0,%1,%2,%3}, {%4,%5,%6,%7}, {%8,%9}, {%0,%1,%2,%3};" \
        : "+f"(c[0]),"+f"(c[1]),"+f"(c[2]),"+f"(c[3]) \
        : "r"(a0),"r"(a1),"r"(a2),"r"(a3), "r"(b0),"r"(b1))

// ---------------- setup ----------------
__global__ __launch_bounds__(256) void k_init(const float* __restrict__ E0u, const float* __restrict__ E0i){
    const int TOT = N_Uc*Dc + N_Ic*Dc;
    int gid = blockIdx.x*256 + threadIdx.x;
    if (gid <= N_Ic) g_ioff[gid] = 0;
    if (gid < 8)     g_acc[gid]  = 0.f;
    float loc = 0.f;
    for (int i = gid; i < TOT; i += gridDim.x*256){
        float v;
        if (i < N_Uc*Dc){ v = E0u[i]; g_EuA[i]=v; g_sEu[i]=v; g_sGu[i]=v; }
        else            { int j=i-N_Uc*Dc; v = E0i[j]; g_EiA[j]=v; g_sEi[j]=v; g_sGi[j]=v; }
        loc += v*v;
    }
    loc = warpSum(loc);
    __shared__ float sw[8];
    int lane = threadIdx.x & 31, wid = threadIdx.x >> 5;
    if (lane==0) sw[wid]=loc;
    __syncthreads();
    if (wid==0){
        float v = lane<8 ? sw[lane] : 0.f;
        v = warpSum(v);
        if (lane==0) atomicAdd(&g_acc[0], v);
    }
}

__global__ __launch_bounds__(256) void k_count(const int* __restrict__ i_idx){
    int j = blockIdx.x*256 + threadIdx.x;
    if (j < NNZc) atomicAdd(&g_ioff[i_idx[j]], 1);
}

__global__ __launch_bounds__(256) void k_scanA(){
    int b = blockIdx.x;
    int i = b*256 + threadIdx.x;
    int cnt = (i < N_Ic) ? g_ioff[i] : 0;
    int lane = threadIdx.x & 31, w = threadIdx.x >> 5;
    int x = cnt;
    #pragma unroll
    for (int o=1;o<32;o<<=1){
        int y = __shfl_up_sync(FULLMASK, x, o);
        if (lane >= o) x += y;
    }
    __shared__ int ws[8];
    if (lane==31) ws[w] = x;
    __syncthreads();
    if (w==0){
        int v = lane<8 ? ws[lane] : 0;
        #pragma unroll
        for (int o=1;o<8;o<<=1){
            int y = __shfl_up_sync(FULLMASK, v, o);
            if (lane >= o) v += y;
        }
        if (lane<8) ws[lane] = v;
    }
    __syncthreads();
    int excl = x - cnt + (w>0 ? ws[w-1] : 0);
    if (i < N_Ic) g_ioff[i] = excl;
    if (threadIdx.x == 255) g_bsum[b] = excl + cnt;
}

__global__ __launch_bounds__(256) void k_scanC(){
    __shared__ int spref;
    int b = blockIdx.x;
    if (threadIdx.x < 32){
        int l = threadIdx.x;
        int i0 = 2*l, i1 = 2*l+1;
        int v0 = (i0 < NB_SCAN && i0 < b) ? g_bsum[i0] : 0;
        int v1 = (i1 < NB_SCAN && i1 < b) ? g_bsum[i1] : 0;
        int s = warpSumI(v0 + v1);
        if (l==0) spref = s;
    }
    __syncthreads();
    int i = b*256 + threadIdx.x;
    if (i < N_Ic){
        int v = g_ioff[i] + spref;
        g_ioff[i] = v; g_icur[i] = v;
    }
    if (i == 0) g_ioff[N_Ic] = NNZc;
}

__global__ __launch_bounds__(256) void k_fill(const int* __restrict__ i_idx){
    int j = blockIdx.x*256 + threadIdx.x;
    if (j < NNZc){
        int p = atomicAdd(&g_icur[i_idx[j]], 1);
        g_ilist[p] = j;
    }
}

// ---------------- per-layer ----------------
__global__ __launch_bounds__(256) void k_feat(int flip, const float* __restrict__ W,
                                              const float* __restrict__ al, const float* __restrict__ ar){
    __shared__ float sW[64*64];
    __shared__ float sh[16*64];
    int tid = threadIdx.x;
    const float* Eu = flip ? g_EuB : g_EuA;
    const float* Ei = flip ? g_EiB : g_EiA;
    int r0 = blockIdx.x*16;
    for (int i=tid;i<4096;i+=256) sW[i]=W[i];
    for (int i=tid;i<1024;i+=256){
        int node = r0 + (i>>6); int k = i&63;
        float v = 0.f;
        if (node < NNc) v = node < N_Uc ? Eu[node*64+k] : Ei[(node-N_Uc)*64+k];
        sh[i] = v;
    }
    __syncthreads();
    int r = tid>>6, c = tid&63;
    float acc[4] = {0.f,0.f,0.f,0.f};
    #pragma unroll
    for (int k=0;k<64;k++){
        float wv = sW[k*64+c];
        acc[0] += sh[ r     *64+k]*wv;
        acc[1] += sh[(r+4 ) *64+k]*wv;
        acc[2] += sh[(r+8 ) *64+k]*wv;
        acc[3] += sh[(r+12)*64+k]*wv;
    }
    float alc = al[c], arc = ar[c];
    #pragma unroll
    for (int rr=0; rr<4; rr++){
        int node = r0 + r + rr*4;
        if (node < NNc){
            float a = acc[rr];
            g_feat[node*64+c] = a;
            float vl = a*alc, vr = a*arc;
            #pragma unroll
            for (int o=8;o;o>>=1){
                vl += __shfl_down_sync(FULLMASK, vl, o, 16);
                vr += __shfl_down_sync(FULLMASK, vr, o, 16);
            }
            if ((c&15)==0){ g_el[node*4+(c>>4)] = vl; g_er[node*4+(c>>4)] = vr; }
        }
    }
}

// fused user+item GAT/LightGCN kernel; doSplit=1 (layer 1) also emits bf16 hi/lo of final sE
__global__ __launch_bounds__(256) void k_ui(int flip, int doSplit, const float* __restrict__ vals,
                                            const int* __restrict__ i_idx){
    __shared__ int    s_u[8][32];
    __shared__ float4 s_a4[8][32];
    __shared__ float  s_v[8][32];
    int lane = threadIdx.x & 31;
    int w = threadIdx.x >> 5;
    const float* Eu = flip ? g_EuB : g_EuA;
    const float* Ei = flip ? g_EiB : g_EiA;
    int h = lane >> 3;

    if (blockIdx.x < NB_U){
        int u = blockIdx.x*8 + w;
        float* EuN = flip ? g_EuA : g_EuB;
        F4 er4 = ldf4(g_er + u*4);
        int src = u;
        if (lane < 16){ src = N_Uc + i_idx[u*16 + lane]; s_v[w][lane] = vals[u*16 + lane]; }
        bool valid = lane < 17;
        F4 a4 = { 0.f,0.f,0.f,0.f };
        if (valid){
            F4 e4 = leaky4(add4(ldf4(g_el + src*4), er4));
            a4 = exp4(e4);
        }
        F4 s4 = warpSum4(a4);
        if (valid){ s_u[w][lane]=src; s_a4[w][lane]=make_float4(a4.x,a4.y,a4.z,a4.w); }
        __syncwarp();
        float g0=0.f, g1=0.f, z0=0.f, z1=0.f;
        #pragma unroll
        for (int k=0;k<16;k++){
            int sk = s_u[w][k];
            float a = ((const float*)&s_a4[w][k])[h];
            float vv = s_v[w][k];
            float2 f2 = ((const float2*)(g_feat + sk*64))[lane];
            float2 i2 = ((const float2*)(Ei + (sk-N_Uc)*64))[lane];
            g0 += a*f2.x;  g1 += a*f2.y;
            z0 += vv*i2.x; z1 += vv*i2.y;
        }
        {
            float a = ((const float*)&s_a4[w][16])[h];
            float2 f2 = ((const float2*)(g_feat + u*64))[lane];
            g0 += a*f2.x; g1 += a*f2.y;
        }
        float sh = comp4(s4, h);
        float2* sg = (float2*)(g_sGu + u*64);
        float2 cg = sg[lane]; cg.x += eluf(g0/sh); cg.y += eluf(g1/sh); sg[lane] = cg;
        float2 eu = ((const float2*)(Eu + u*64))[lane];
        float2 e; e.x = eu.x + z0; e.y = eu.y + z1;
        ((float2*)(EuN + u*64))[lane] = e;
        float2* se = (float2*)(g_sEu + u*64);
        float2 cs = se[lane]; cs.x += e.x; cs.y += e.y; se[lane] = cs;
        if (doSplit){
            ((uint*)(g_Ehi + u*64))[lane] = pack_hi2(cs.x, cs.y);
            ((uint*)(g_Elo + u*64))[lane] = pack_lo2(cs.x, cs.y);
        }
    } else {
        int i = (blockIdx.x - NB_U)*8 + w;
        if (i >= N_Ic) return;
        int node = N_Uc + i;
        float* EiN = flip ? g_EiA : g_EiB;
        int off = g_ioff[i];
        int cnt = g_ioff[i+1] - off;
        int deg = cnt + 1;
        F4 er4 = ldf4(g_er + node*4);
        float g0=0.f, g1=0.f, z0=0.f, z1=0.f;
        F4 ssum = {0.f,0.f,0.f,0.f};
        for (int base=0; base<deg; base+=32){
            int k = base + lane;
            if (k < deg){
                int src; float vv;
                if (k < cnt){
                    int j = g_ilist[off+k];
                    src = j >> 4; vv = vals[j];
                } else { src = node; vv = 0.f; }
                F4 e4 = leaky4(add4(ldf4(g_el + src*4), er4));
                F4 a4 = exp4(e4);
                ssum = add4(ssum, a4);
                s_u[w][lane] = src;
                s_a4[w][lane] = make_float4(a4.x, a4.y, a4.z, a4.w);
                s_v[w][lane] = vv;
            }
            __syncwarp();
            int kmax = min(32, deg - base);
            for (int kk=0; kk<kmax; kk++){
                int sk = s_u[w][kk];
                float a = ((const float*)&s_a4[w][kk])[h];
                float2 f2 = ((const float2*)(g_feat + sk*64))[lane];
                g0 += a*f2.x; g1 += a*f2.y;
                if (sk < N_Uc){
                    float vv = s_v[w][kk];
                    float2 u2 = ((const float2*)(Eu + sk*64))[lane];
                    z0 += vv*u2.x; z1 += vv*u2.y;
                }
            }
            __syncwarp();
        }
        F4 s4 = warpSum4(ssum);
        float sh = comp4(s4, h);
        float2* sg = (float2*)(g_sGi + i*64);
        float2 cg = sg[lane]; cg.x += eluf(g0/sh); cg.y += eluf(g1/sh); sg[lane] = cg;
        float2 ei = ((const float2*)(Ei + i*64))[lane];
        float2 e; e.x = ei.x + z0; e.y = ei.y + z1;
        ((float2*)(EiN + i*64))[lane] = e;
        float2* se = (float2*)(g_sEi + i*64);
        float2 cs = se[lane]; cs.x += e.x; cs.y += e.y; se[lane] = cs;
        if (doSplit){
            ((uint*)(g_Ehi + node*64))[lane] = pack_hi2(cs.x, cs.y);
            ((uint*)(g_Elo + node*64))[lane] = pack_lo2(cs.x, cs.y);
        }
    }
}

// ---------------- bf16 split (queries only; E fused into k_ui layer 1) ----------------
__global__ __launch_bounds__(256) void k_splitQ(const int* __restrict__ uids, const int* __restrict__ iids){
    int t = blockIdx.x*256 + threadIdx.x;
    const int NQ4 = NQ*Dc/4;
    if (t >= NQ4) return;
    int idx = t*4;
    int q = idx >> 6, k = idx & 63;
    const float* src = ((q < BQ) ? (g_sGu + uids[q]*64) : (g_sGi + iids[q-BQ]*64)) + k;
    float4 v = *(const float4*)src;
    uint h0 = pack_hi2(v.x, v.y), h1 = pack_hi2(v.z, v.w);
    uint l0 = pack_lo2(v.x, v.y), l1 = pack_lo2(v.z, v.w);
    *(uint2*)(g_Qhi + idx) = make_uint2(h0, h1);
    *(uint2*)(g_Qlo + idx) = make_uint2(l0, l1);
}

// ---------------- loss: bf16 split MMA + fixed-shift LSE (R10 single-buffer version) ----------------
__global__ __launch_bounds__(256,2) void k_mma(){
    __shared__ uint sEhi[64*36];
    __shared__ uint sElo[64*36];
    int bx = blockIdx.x;
    int tid = threadIdx.x;
    int lane = tid & 31, w = tid >> 5;
    int qt, split, qOff, eOff;
    if (bx < 16*JT_U){ qt = bx / JT_U; split = bx % JT_U; qOff = 0;    eOff = 0; }
    else { int b = bx - 16*JT_U; qt = b / JT_I; split = b % JT_I; qOff = BQ; eOff = N_Uc; }
    int rowBase = eOff + split*CHUNK;
    int rowEnd  = rowBase + CHUNK;

    int qrow = qOff + qt*128 + w*16 + (lane>>2);
    const uint* Qh = (const uint*)g_Qhi;
    const uint* Ql = (const uint*)g_Qlo;
    uint Ahi[4][4], Alo[4][4];
    #pragma unroll
    for (int ks=0; ks<4; ks++){
        int k2 = ks*8 + (lane&3);
        Ahi[ks][0] = Qh[ qrow   *32 + k2    ];
        Ahi[ks][1] = Qh[(qrow+8)*32 + k2    ];
        Ahi[ks][2] = Qh[ qrow   *32 + k2 + 4];
        Ahi[ks][3] = Qh[(qrow+8)*32 + k2 + 4];
        Alo[ks][0] = Ql[ qrow   *32 + k2    ];
        Alo[ks][1] = Ql[(qrow+8)*32 + k2    ];
        Alo[ks][2] = Ql[ qrow   *32 + k2 + 4];
        Alo[ks][3] = Ql[(qrow+8)*32 + k2 + 4];
    }

    int L8 = lane & 7, g = lane >> 3;
    int j_off = ((g & 2) << 2) + L8;
    int k_off2 = (g & 1) * 16;
    uint laneB = (uint)(j_off*144 + k_off2);
    uint baseHi = smem_u32(sEhi) + laneB;
    uint baseLo = smem_u32(sElo) + laneB;

    int rr = tid >> 2, cc = tid & 3;
    const uint4* Eh4 = (const uint4*)g_Ehi;
    const uint4* El4 = (const uint4*)g_Elo;
    uint4 rp0, rp1, rp2, rp3;
    {
        int jj = rowBase + rr;
        bool v = jj < rowEnd;
        long gi = (long)jj*8 + cc*2;
        rp0 = v ? Eh4[gi]   : make_uint4(0,0,0,0);
        rp1 = v ? Eh4[gi+1] : make_uint4(0,0,0,0);
        rp2 = v ? El4[gi]   : make_uint4(0,0,0,0);
        rp3 = v ? El4[gi+1] : make_uint4(0,0,0,0);
    }

    float s0 = 0.f, s1 = 0.f;

    for (int jt=0; jt<NTILES; jt++){
        __syncthreads();
        {
            uint so = rr*36 + cc*8;
            *(uint4*)(sEhi + so)     = rp0;
            *(uint4*)(sEhi + so + 4) = rp1;
            *(uint4*)(sElo + so)     = rp2;
            *(uint4*)(sElo + so + 4) = rp3;
        }
        __syncthreads();
        if (jt+1 < NTILES){
            int jj = rowBase + (jt+1)*64 + rr;
            bool v = jj < rowEnd;
            long gi = (long)jj*8 + cc*2;
            rp0 = v ? Eh4[gi]   : make_uint4(0,0,0,0);
            rp1 = v ? Eh4[gi+1] : make_uint4(0,0,0,0);
            rp2 = v ? El4[gi]   : make_uint4(0,0,0,0);
            rp3 = v ? El4[gi+1] : make_uint4(0,0,0,0);
        }

        float acc[8][4];
        #pragma unroll
        for (int n=0;n<8;n++){ acc[n][0]=0.f; acc[n][1]=0.f; acc[n][2]=0.f; acc[n][3]=0.f; }

        #pragma unroll
        for (int ks=0; ks<4; ks++){
            uint kb = ks*32;
            #pragma unroll
            for (int p=0; p<4; p++){
                uint bh0,bh1,bh2,bh3, bl0,bl1,bl2,bl3;
                LDSM4(bh0,bh1,bh2,bh3, baseHi + p*2304 + kb);
                LDSM4(bl0,bl1,bl2,bl3, baseLo + p*2304 + kb);
                MMA16816(acc[2*p],   Ahi[ks][0],Ahi[ks][1],Ahi[ks][2],Ahi[ks][3], bh0,bh1);
                MMA16816(acc[2*p],   Alo[ks][0],Alo[ks][1],Alo[ks][2],Alo[ks][3], bh0,bh1);
                MMA16816(acc[2*p],   Ahi[ks][0],Ahi[ks][1],Ahi[ks][2],Ahi[ks][3], bl0,bl1);
                MMA16816(acc[2*p+1], Ahi[ks][0],Ahi[ks][1],Ahi[ks][2],Ahi[ks][3], bh2,bh3);
                MMA16816(acc[2*p+1], Alo[ks][0],Alo[ks][1],Alo[ks][2],Alo[ks][3], bh2,bh3);
                MMA16816(acc[2*p+1], Ahi[ks][0],Ahi[ks][1],Ahi[ks][2],Ahi[ks][3], bl2,bl3);
            }
        }

        int jl0 = jt*64 + 2*(lane&3);
        #pragma unroll
        for (int n=0;n<8;n++){
            float v0 = acc[n][0], v1 = acc[n][1], v2 = acc[n][2], v3 = acc[n][3];
            if (jt == NTILES-1){
                int jl = jl0 + n*8;
                if (jl   >= CHUNK){ v0 = NEGINF; v2 = NEGINF; }
                if (jl+1 >= CHUNK){ v1 = NEGINF; v3 = NEGINF; }
            }
            s0 += __expf(fmaf(v0, INV_TEMP, -LSE_SHIFT)) + __expf(fmaf(v1, INV_TEMP, -LSE_SHIFT));
            s1 += __expf(fmaf(v2, INV_TEMP, -LSE_SHIFT)) + __expf(fmaf(v3, INV_TEMP, -LSE_SHIFT));
        }
    }

    #pragma unroll
    for (int o=1; o<4; o<<=1){
        s0 += __shfl_xor_sync(FULLMASK, s0, o);
        s1 += __shfl_xor_sync(FULLMASK, s1, o);
    }
    if ((lane & 3) == 0){
        int gq = qOff + qt*128 + w*16 + (lane>>2);
        g_pm[gq*PSTR + split] = LSE_SHIFT;
        g_ps[gq*PSTR + split] = s0;
        g_pm[(gq+8)*PSTR + split] = LSE_SHIFT;
        g_ps[(gq+8)*PSTR + split] = s1;
    }
}

__global__ __launch_bounds__(256) void k_finsc(const int* __restrict__ uids, const int* __restrict__ iids,
                                               const int* __restrict__ pos, const int* __restrict__ neg){
    if (blockIdx.x < 16){
        int q = blockIdx.x*256 + threadIdx.x;
        int T = (q < BQ) ? JT_U : JT_I;
        float M = NEGINF;
        for (int t=0;t<T;t++) M = fmaxf(M, g_pm[q*PSTR+t]);
        float S = 0.f;
        for (int t=0;t<T;t++) S += g_ps[q*PSTR+t]*expf(g_pm[q*PSTR+t]-M);
        float lse = M + logf(S);
        float dmax = fmaxf(lse, LOG_EPS_C);
        float dmin = fminf(lse, LOG_EPS_C);
        float v = dmax + log1pf(expf(dmin - dmax));
        v = warpSum(v);
        __shared__ float sw[8];
        int lane = threadIdx.x & 31, wid = threadIdx.x >> 5;
        if (lane==0) sw[wid]=v;
        __syncthreads();
        if (wid==0){
            float x = lane<8 ? sw[lane] : 0.f;
            x = warpSum(x);
            if (lane==0) atomicAdd(&g_acc[blockIdx.x < 8 ? 1 : 2], x);
        }
    } else {
        int q = (blockIdx.x-16)*8 + (threadIdx.x>>5);
        if (q >= BQ) return;
        int lane = threadIdx.x & 31;
        int u = uids[q], it = iids[q], p = pos[q], ng = neg[q];
        const float* Gu = g_sGu + u*64;
        const float* Eu = g_sEu + u*64;
        const float* Gi = g_sGi + it*64;
        const float* Eit = g_sEi + it*64;
        const float* Ep = g_sEi + p*64;
        const float* En = g_sEi + ng*64;
        float du=0.f, di=0.f, dd=0.f;
        #pragma unroll
        for (int t=0;t<2;t++){
            int rr = lane + 32*t;
            float eu = Eu[rr];
            du += Gu[rr]*eu;
            di += Gi[rr]*Eit[rr];
            dd += eu*(Ep[rr]-En[rr]);
        }
        du = warpSum(du); di = warpSum(di); dd = warpSum(dd);
        if (lane==0){
            atomicAdd(&g_acc[3], du);
            atomicAdd(&g_acc[4], di);
            float x = -dd;
            float sp = fmaxf(x,0.f) + log1pf(expf(-fabsf(x)));
            atomicAdd(&g_acc[5], sp);
        }
    }
}

__global__ void k_out(float* out){
    float Bf = (float)BQ;
    float neg_score = g_acc[1]/Bf + g_acc[2]/Bf;
    float pos_score = (g_acc[3] + g_acc[4]) * INV_TEMP / Bf;
    float loss_s = neg_score - pos_score;
    float loss_r = g_acc[5]/Bf;
    float reg = 1e-7f * g_acc[0];
    out[0] = loss_r + 0.2f*loss_s + reg;
    out[1] = loss_r;
    out[2] = 0.2f*loss_s;
}

// ---------------- launch ----------------
extern "C" void kernel_launch(void* const* d_in, const int* in_sizes, int n_in,
                              void* d_out, int out_size){
    const float* E_u_0    = (const float*)d_in[0];
    const float* E_i_0    = (const float*)d_in[1];
    const float* adj_vals = (const float*)d_in[2];
    const float* W        = (const float*)d_in[3];
    const float* attn_l   = (const float*)d_in[4];
    const float* attn_r   = (const float*)d_in[5];
    const int*   i_idx    = (const int*)d_in[7];
    const int*   uids     = (const int*)d_in[10];
    const int*   iids     = (const int*)d_in[11];
    const int*   pos      = (const int*)d_in[12];
    const int*   neg      = (const int*)d_in[13];
    float* out = (float*)d_out;

    k_init  <<<1024, 256>>>(E_u_0, E_i_0);                 // 0
    k_count <<<(NNZc+255)/256, 256>>>(i_idx);              // 1
    k_feat  <<<(NNc+15)/16, 256>>>(0, W, attn_l, attn_r);  // 2
    k_scanA <<<NB_SCAN, 256>>>();                          // 3
    k_scanC <<<NB_SCAN, 256>>>();                          // 4
    k_fill  <<<(NNZc+255)/256, 256>>>(i_idx);              // 5
    k_ui    <<<NB_U + NB_I, 256>>>(0, 0, adj_vals, i_idx); // 6
    k_feat  <<<(NNc+15)/16, 256>>>(1, W, attn_l, attn_r);  // 7
    k_ui    <<<NB_U + NB_I, 256>>>(1, 1, adj_vals, i_idx); // 8
    k_splitQ<<<(NQ*Dc/4 + 255)/256, 256>>>(uids, iids);    // 9
    k_mma   <<<16*JT_U + 16*JT_I, 256>>>();                // 10
    k_finsc <<<16 + BQ/8, 256>>>(uids, iids, pos, neg);    // 11
    k_out   <<<1, 1>>>(out);                               // 12
}

// round 14
// speedup vs baseline: 1.1088x; 1.0829x over previous
#include <cuda_runtime.h>
#include <cuda_bf16.h>
#include <math.h>

#define N_Uc 30000
#define N_Ic 15000
#define NNc  45000
#define Dc   64
#define NNZc 480000
#define BQ   2048
#define NQ   (2*BQ)
#define JT_U 12
#define JT_I 6
#define PSTR 16
#define CHUNK 2500
#define NTILES 40
#define NB_SCAN 59
#define NB_U 3750
#define NB_I 1875
#define INV_TEMP 5.0f
#define LSE_SHIFT 40.0f
#define NEG_SLOPE_C 0.2f
#define LOG_EPS_C (-18.420680743952367f)
#define FULLMASK 0xffffffffu
#define NEGINF (-INFINITY)

typedef unsigned long long ull;
typedef unsigned int uint;
typedef unsigned short ushort;

// ---------------- scratch ----------------
__device__ float g_EuA[N_Uc*Dc], g_EuB[N_Uc*Dc];
__device__ float g_EiA[N_Ic*Dc], g_EiB[N_Ic*Dc];
__device__ float g_sEu[N_Uc*Dc], g_sEi[N_Ic*Dc];
__device__ float g_sGu[N_Uc*Dc], g_sGi[N_Ic*Dc];
__device__ float g_feat[NNc*Dc];
__device__ float g_el[NNc*4], g_er[NNc*4];
__device__ int   g_ioff[N_Ic+1];
__device__ int   g_icur[N_Ic];
__device__ int   g_ilist[NNZc];
__device__ int   g_bsum[64];
__device__ float g_pm[NQ*PSTR], g_ps[NQ*PSTR];
__device__ float g_acc[8];
__device__ ushort g_Ehi[NNc*Dc], g_Elo[NNc*Dc];
__device__ ushort g_Qhi[NQ*Dc],  g_Qlo[NQ*Dc];

// ---------------- helpers ----------------
__device__ __forceinline__ float warpSum(float v){
    #pragma unroll
    for (int o=16;o;o>>=1) v += __shfl_xor_sync(FULLMASK, v, o);
    return v;
}
__device__ __forceinline__ int warpSumI(int v){
    #pragma unroll
    for (int o=16;o;o>>=1) v += __shfl_xor_sync(FULLMASK, v, o);
    return v;
}
__device__ __forceinline__ float leakyf(float x){ return x > 0.f ? x : NEG_SLOPE_C*x; }
__device__ __forceinline__ float eluf(float x){ return x > 0.f ? x : expm1f(x); }

struct F4 { float x,y,z,w; };
__device__ __forceinline__ F4 ldf4(const float* p){ float4 v = *(const float4*)p; return {v.x,v.y,v.z,v.w}; }
__device__ __forceinline__ F4 leaky4(F4 a){ return { leakyf(a.x), leakyf(a.y), leakyf(a.z), leakyf(a.w) }; }
__device__ __forceinline__ F4 add4(F4 a, F4 b){ return { a.x+b.x, a.y+b.y, a.z+b.z, a.w+b.w }; }
__device__ __forceinline__ F4 exp4(F4 a){ return { __expf(a.x), __expf(a.y), __expf(a.z), __expf(a.w) }; }
__device__ __forceinline__ F4 warpSum4(F4 v){
    v.x = warpSum(v.x); v.y = warpSum(v.y); v.z = warpSum(v.z); v.w = warpSum(v.w);
    return v;
}
__device__ __forceinline__ float comp4(F4 v, int h){
    return h==0 ? v.x : (h==1 ? v.y : (h==2 ? v.z : v.w));
}
__device__ __forceinline__ unsigned smem_u32(const void* p){
    return (unsigned)__cvta_generic_to_shared(p);
}

#define LDSM4(r0,r1,r2,r3,addr) \
    asm volatile("ldmatrix.sync.aligned.m8n8.x4.shared.b16 {%0,%1,%2,%3}, [%4];" \
        : "=r"(r0),"=r"(r1),"=r"(r2),"=r"(r3) : "r"(addr))

#define MMA16816(c,a0,a1,a2,a3,b0,b1) \
    asm volatile("mma.sync.aligned.m16n8k16.row.col.f32.bf16.bf16.f32 " \
        "{%0,%1,%2,%3}, {%4,%5,%6,%7}, {%8,%9}, {%0,%1,%2,%3};" \
        : "+f"(c[0]),"+f"(c[1]),"+f"(c[2]),"+f"(c[3]) \
        : "r"(a0),"r"(a1),"r"(a2),"r"(a3), "r"(b0),"r"(b1))

// ---------------- setup ----------------
__global__ __launch_bounds__(256) void k_init(const float* __restrict__ E0u, const float* __restrict__ E0i){
    const int TOT = N_Uc*Dc + N_Ic*Dc;
    int gid = blockIdx.x*256 + threadIdx.x;
    if (gid <= N_Ic) g_ioff[gid] = 0;
    if (gid < 8)     g_acc[gid]  = 0.f;
    float loc = 0.f;
    for (int i = gid; i < TOT; i += gridDim.x*256){
        float v;
        if (i < N_Uc*Dc){ v = E0u[i]; g_EuA[i]=v; g_sEu[i]=v; g_sGu[i]=v; }
        else            { int j=i-N_Uc*Dc; v = E0i[j]; g_EiA[j]=v; g_sEi[j]=v; g_sGi[j]=v; }
        loc += v*v;
    }
    loc = warpSum(loc);
    __shared__ float sw[8];
    int lane = threadIdx.x & 31, wid = threadIdx.x >> 5;
    if (lane==0) sw[wid]=loc;
    __syncthreads();
    if (wid==0){
        float v = lane<8 ? sw[lane] : 0.f;
        v = warpSum(v);
        if (lane==0) atomicAdd(&g_acc[0], v);
    }
}

__global__ __launch_bounds__(256) void k_count(const int* __restrict__ i_idx){
    int j = blockIdx.x*256 + threadIdx.x;
    if (j < NNZc) atomicAdd(&g_ioff[i_idx[j]], 1);
}

__global__ __launch_bounds__(256) void k_scanA(){
    int b = blockIdx.x;
    int i = b*256 + threadIdx.x;
    int cnt = (i < N_Ic) ? g_ioff[i] : 0;
    int lane = threadIdx.x & 31, w = threadIdx.x >> 5;
    int x = cnt;
    #pragma unroll
    for (int o=1;o<32;o<<=1){
        int y = __shfl_up_sync(FULLMASK, x, o);
        if (lane >= o) x += y;
    }
    __shared__ int ws[8];
    if (lane==31) ws[w] = x;
    __syncthreads();
    if (w==0){
        int v = lane<8 ? ws[lane] : 0;
        #pragma unroll
        for (int o=1;o<8;o<<=1){
            int y = __shfl_up_sync(FULLMASK, v, o);
            if (lane >= o) v += y;
        }
        if (lane<8) ws[lane] = v;
    }
    __syncthreads();
    int excl = x - cnt + (w>0 ? ws[w-1] : 0);
    if (i < N_Ic) g_ioff[i] = excl;
    if (threadIdx.x == 255) g_bsum[b] = excl + cnt;
}

__global__ __launch_bounds__(256) void k_scanC(){
    __shared__ int spref;
    int b = blockIdx.x;
    if (threadIdx.x < 32){
        int l = threadIdx.x;
        int i0 = 2*l, i1 = 2*l+1;
        int v0 = (i0 < NB_SCAN && i0 < b) ? g_bsum[i0] : 0;
        int v1 = (i1 < NB_SCAN && i1 < b) ? g_bsum[i1] : 0;
        int s = warpSumI(v0 + v1);
        if (l==0) spref = s;
    }
    __syncthreads();
    int i = b*256 + threadIdx.x;
    if (i < N_Ic){
        int v = g_ioff[i] + spref;
        g_ioff[i] = v; g_icur[i] = v;
    }
    if (i == 0) g_ioff[N_Ic] = NNZc;
}

__global__ __launch_bounds__(256) void k_fill(const int* __restrict__ i_idx){
    int j = blockIdx.x*256 + threadIdx.x;
    if (j < NNZc){
        int p = atomicAdd(&g_icur[i_idx[j]], 1);
        g_ilist[p] = j;
    }
}

// ---------------- per-layer ----------------
__global__ __launch_bounds__(256) void k_feat(int flip, const float* __restrict__ W,
                                              const float* __restrict__ al, const float* __restrict__ ar){
    __shared__ float sW[64*64];
    __shared__ float sh[16*64];
    int tid = threadIdx.x;
    const float* Eu = flip ? g_EuB : g_EuA;
    const float* Ei = flip ? g_EiB : g_EiA;
    int r0 = blockIdx.x*16;
    for (int i=tid;i<4096;i+=256) sW[i]=W[i];
    for (int i=tid;i<1024;i+=256){
        int node = r0 + (i>>6); int k = i&63;
        float v = 0.f;
        if (node < NNc) v = node < N_Uc ? Eu[node*64+k] : Ei[(node-N_Uc)*64+k];
        sh[i] = v;
    }
    __syncthreads();
    int r = tid>>6, c = tid&63;
    float acc[4] = {0.f,0.f,0.f,0.f};
    #pragma unroll
    for (int k=0;k<64;k++){
        float wv = sW[k*64+c];
        acc[0] += sh[ r     *64+k]*wv;
        acc[1] += sh[(r+4 ) *64+k]*wv;
        acc[2] += sh[(r+8 ) *64+k]*wv;
        acc[3] += sh[(r+12)*64+k]*wv;
    }
    float alc = al[c], arc = ar[c];
    #pragma unroll
    for (int rr=0; rr<4; rr++){
        int node = r0 + r + rr*4;
        if (node < NNc){
            float a = acc[rr];
            g_feat[node*64+c] = a;
            float vl = a*alc, vr = a*arc;
            #pragma unroll
            for (int o=8;o;o>>=1){
                vl += __shfl_down_sync(FULLMASK, vl, o, 16);
                vr += __shfl_down_sync(FULLMASK, vr, o, 16);
            }
            if ((c&15)==0){ g_el[node*4+(c>>4)] = vl; g_er[node*4+(c>>4)] = vr; }
        }
    }
}

// fused user+item GAT/LightGCN kernel: blocks [0,NB_U) user, [NB_U,NB_U+NB_I) item
__global__ __launch_bounds__(256) void k_ui(int flip, const float* __restrict__ vals,
                                            const int* __restrict__ i_idx){
    __shared__ int    s_u[8][32];
    __shared__ float4 s_a4[8][32];
    __shared__ float  s_v[8][32];
    int lane = threadIdx.x & 31;
    int w = threadIdx.x >> 5;
    const float* Eu = flip ? g_EuB : g_EuA;
    const float* Ei = flip ? g_EiB : g_EiA;
    int h = lane >> 3;

    if (blockIdx.x < NB_U){
        // ---------------- user ----------------
        int u = blockIdx.x*8 + w;
        float* EuN = flip ? g_EuA : g_EuB;
        F4 er4 = ldf4(g_er + u*4);
        int src = u;
        if (lane < 16){ src = N_Uc + i_idx[u*16 + lane]; s_v[w][lane] = vals[u*16 + lane]; }
        bool valid = lane < 17;
        F4 a4 = { 0.f,0.f,0.f,0.f };
        if (valid){
            F4 e4 = leaky4(add4(ldf4(g_el + src*4), er4));
            a4 = exp4(e4);
        }
        F4 s4 = warpSum4(a4);
        if (valid){ s_u[w][lane]=src; s_a4[w][lane]=make_float4(a4.x,a4.y,a4.z,a4.w); }
        __syncwarp();
        float g0=0.f, g1=0.f, z0=0.f, z1=0.f;
        #pragma unroll
        for (int k=0;k<16;k++){
            int sk = s_u[w][k];
            float a = ((const float*)&s_a4[w][k])[h];
            float vv = s_v[w][k];
            float2 f2 = ((const float2*)(g_feat + sk*64))[lane];
            float2 i2 = ((const float2*)(Ei + (sk-N_Uc)*64))[lane];
            g0 += a*f2.x;  g1 += a*f2.y;
            z0 += vv*i2.x; z1 += vv*i2.y;
        }
        {
            float a = ((const float*)&s_a4[w][16])[h];
            float2 f2 = ((const float2*)(g_feat + u*64))[lane];
            g0 += a*f2.x; g1 += a*f2.y;
        }
        float sh = comp4(s4, h);
        float2* sg = (float2*)(g_sGu + u*64);
        float2 cg = sg[lane]; cg.x += eluf(g0/sh); cg.y += eluf(g1/sh); sg[lane] = cg;
        float2 eu = ((const float2*)(Eu + u*64))[lane];
        float2 e; e.x = eu.x + z0; e.y = eu.y + z1;
        ((float2*)(EuN + u*64))[lane] = e;
        float2* se = (float2*)(g_sEu + u*64);
        float2 cs = se[lane]; cs.x += e.x; cs.y += e.y; se[lane] = cs;
    } else {
        // ---------------- item ----------------
        int i = (blockIdx.x - NB_U)*8 + w;
        if (i >= N_Ic) return;
        int node = N_Uc + i;
        float* EiN = flip ? g_EiA : g_EiB;
        int off = g_ioff[i];
        int cnt = g_ioff[i+1] - off;
        int deg = cnt + 1;
        F4 er4 = ldf4(g_er + node*4);
        float g0=0.f, g1=0.f, z0=0.f, z1=0.f;
        F4 ssum = {0.f,0.f,0.f,0.f};
        for (int base=0; base<deg; base+=32){
            int k = base + lane;
            if (k < deg){
                int src; float vv;
                if (k < cnt){
                    int j = g_ilist[off+k];
                    src = j >> 4; vv = vals[j];
                } else { src = node; vv = 0.f; }
                F4 e4 = leaky4(add4(ldf4(g_el + src*4), er4));
                F4 a4 = exp4(e4);
                ssum = add4(ssum, a4);
                s_u[w][lane] = src;
                s_a4[w][lane] = make_float4(a4.x, a4.y, a4.z, a4.w);
                s_v[w][lane] = vv;
            }
            __syncwarp();
            int kmax = min(32, deg - base);
            for (int kk=0; kk<kmax; kk++){
                int sk = s_u[w][kk];
                float a = ((const float*)&s_a4[w][kk])[h];
                float2 f2 = ((const float2*)(g_feat + sk*64))[lane];
                g0 += a*f2.x; g1 += a*f2.y;
                if (sk < N_Uc){
                    float vv = s_v[w][kk];
                    float2 u2 = ((const float2*)(Eu + sk*64))[lane];
                    z0 += vv*u2.x; z1 += vv*u2.y;
                }
            }
            __syncwarp();
        }
        F4 s4 = warpSum4(ssum);
        float sh = comp4(s4, h);
        float2* sg = (float2*)(g_sGi + i*64);
        float2 cg = sg[lane]; cg.x += eluf(g0/sh); cg.y += eluf(g1/sh); sg[lane] = cg;
        float2 ei = ((const float2*)(Ei + i*64))[lane];
        float2 e; e.x = ei.x + z0; e.y = ei.y + z1;
        ((float2*)(EiN + i*64))[lane] = e;
        float2* se = (float2*)(g_sEi + i*64);
        float2 cs = se[lane]; cs.x += e.x; cs.y += e.y; se[lane] = cs;
    }
}

// ---------------- bf16 split (fused E + Q) ----------------
__global__ __launch_bounds__(256) void k_split(const int* __restrict__ uids, const int* __restrict__ iids){
    const int NE = NNc*Dc/4;
    const int NQ4 = NQ*Dc/4;
    int t = blockIdx.x*256 + threadIdx.x;
    const float* src;
    ushort *dhi, *dlo;
    int idx;
    if (t < NE){
        idx = t*4;
        int row = idx >> 6, k = idx & 63;
        src = ((row < N_Uc) ? (g_sEu + row*64) : (g_sEi + (row-N_Uc)*64)) + k;
        dhi = g_Ehi + idx; dlo = g_Elo + idx;
    } else {
        int t2 = t - NE;
        if (t2 >= NQ4) return;
        idx = t2*4;
        int q = idx >> 6, k = idx & 63;
        src = ((q < BQ) ? (g_sGu + uids[q]*64) : (g_sGi + iids[q-BQ]*64)) + k;
        dhi = g_Qhi + idx; dlo = g_Qlo + idx;
    }
    float4 v = *(const float4*)src;
    float vv[4] = {v.x, v.y, v.z, v.w};
    uint h2[2], l2[2];
    #pragma unroll
    for (int p=0;p<2;p++){
        __nv_bfloat16 h0 = __float2bfloat16_rn(vv[2*p]);
        __nv_bfloat16 h1 = __float2bfloat16_rn(vv[2*p+1]);
        __nv_bfloat16 l0 = __float2bfloat16_rn(vv[2*p]   - __bfloat162float(h0));
        __nv_bfloat16 l1 = __float2bfloat16_rn(vv[2*p+1] - __bfloat162float(h1));
        h2[p] = (uint)__bfloat16_as_ushort(h0) | ((uint)__bfloat16_as_ushort(h1) << 16);
        l2[p] = (uint)__bfloat16_as_ushort(l0) | ((uint)__bfloat16_as_ushort(l1) << 16);
    }
    *(uint2*)dhi = make_uint2(h2[0], h2[1]);
    *(uint2*)dlo = make_uint2(l2[0], l2[1]);
}

// ---------------- loss: bf16 split MMA + fixed-shift LSE ----------------
__global__ __launch_bounds__(256,2) void k_mma(){
    __shared__ uint sEhi[64*36];
    __shared__ uint sElo[64*36];
    int bx = blockIdx.x;
    int tid = threadIdx.x;
    int lane = tid & 31, w = tid >> 5;
    int qt, split, qOff, eOff;
    if (bx < 16*JT_U){ qt = bx / JT_U; split = bx % JT_U; qOff = 0;    eOff = 0; }
    else { int b = bx - 16*JT_U; qt = b / JT_I; split = b % JT_I; qOff = BQ; eOff = N_Uc; }
    int rowBase = eOff + split*CHUNK;
    int rowEnd  = rowBase + CHUNK;

    int qrow = qOff + qt*128 + w*16 + (lane>>2);
    const uint* Qh = (const uint*)g_Qhi;
    const uint* Ql = (const uint*)g_Qlo;
    uint Ahi[4][4], Alo[4][4];
    #pragma unroll
    for (int ks=0; ks<4; ks++){
        int k2 = ks*8 + (lane&3);
        Ahi[ks][0] = Qh[ qrow   *32 + k2    ];
        Ahi[ks][1] = Qh[(qrow+8)*32 + k2    ];
        Ahi[ks][2] = Qh[ qrow   *32 + k2 + 4];
        Ahi[ks][3] = Qh[(qrow+8)*32 + k2 + 4];
        Alo[ks][0] = Ql[ qrow   *32 + k2    ];
        Alo[ks][1] = Ql[(qrow+8)*32 + k2    ];
        Alo[ks][2] = Ql[ qrow   *32 + k2 + 4];
        Alo[ks][3] = Ql[(qrow+8)*32 + k2 + 4];
    }

    int L8 = lane & 7, g = lane >> 3;
    int j_off = ((g & 2) << 2) + L8;
    int k_off2 = (g & 1) * 16;
    uint laneB = (uint)(j_off*144 + k_off2);
    uint baseHi = smem_u32(sEhi) + laneB;
    uint baseLo = smem_u32(sElo) + laneB;

    int rr = tid >> 2, cc = tid & 3;
    const uint4* Eh4 = (const uint4*)g_Ehi;
    const uint4* El4 = (const uint4*)g_Elo;
    uint4 rp0, rp1, rp2, rp3;
    {
        int jj = rowBase + rr;
        bool v = jj < rowEnd;
        long gi = (long)jj*8 + cc*2;
        rp0 = v ? Eh4[gi]   : make_uint4(0,0,0,0);
        rp1 = v ? Eh4[gi+1] : make_uint4(0,0,0,0);
        rp2 = v ? El4[gi]   : make_uint4(0,0,0,0);
        rp3 = v ? El4[gi+1] : make_uint4(0,0,0,0);
    }

    float s0 = 0.f, s1 = 0.f;

    for (int jt=0; jt<NTILES; jt++){
        __syncthreads();
        {
            uint so = rr*36 + cc*8;
            *(uint4*)(sEhi + so)     = rp0;
            *(uint4*)(sEhi + so + 4) = rp1;
            *(uint4*)(sElo + so)     = rp2;
            *(uint4*)(sElo + so + 4) = rp3;
        }
        __syncthreads();
        if (jt+1 < NTILES){
            int jj = rowBase + (jt+1)*64 + rr;
            bool v = jj < rowEnd;
            long gi = (long)jj*8 + cc*2;
            rp0 = v ? Eh4[gi]   : make_uint4(0,0,0,0);
            rp1 = v ? Eh4[gi+1] : make_uint4(0,0,0,0);
            rp2 = v ? El4[gi]   : make_uint4(0,0,0,0);
            rp3 = v ? El4[gi+1] : make_uint4(0,0,0,0);
        }

        float acc[8][4];
        #pragma unroll
        for (int n=0;n<8;n++){ acc[n][0]=0.f; acc[n][1]=0.f; acc[n][2]=0.f; acc[n][3]=0.f; }

        #pragma unroll
        for (int ks=0; ks<4; ks++){
            uint kb = ks*32;
            #pragma unroll
            for (int p=0; p<4; p++){
                uint bh0,bh1,bh2,bh3, bl0,bl1,bl2,bl3;
                LDSM4(bh0,bh1,bh2,bh3, baseHi + p*2304 + kb);
                LDSM4(bl0,bl1,bl2,bl3, baseLo + p*2304 + kb);
                MMA16816(acc[2*p],   Ahi[ks][0],Ahi[ks][1],Ahi[ks][2],Ahi[ks][3], bh0,bh1);
                MMA16816(acc[2*p],   Alo[ks][0],Alo[ks][1],Alo[ks][2],Alo[ks][3], bh0,bh1);
                MMA16816(acc[2*p],   Ahi[ks][0],Ahi[ks][1],Ahi[ks][2],Ahi[ks][3], bl0,bl1);
                MMA16816(acc[2*p+1], Ahi[ks][0],Ahi[ks][1],Ahi[ks][2],Ahi[ks][3], bh2,bh3);
                MMA16816(acc[2*p+1], Alo[ks][0],Alo[ks][1],Alo[ks][2],Alo[ks][3], bh2,bh3);
                MMA16816(acc[2*p+1], Ahi[ks][0],Ahi[ks][1],Ahi[ks][2],Ahi[ks][3], bl2,bl3);
            }
        }

        int jl0 = jt*64 + 2*(lane&3);
        #pragma unroll
        for (int n=0;n<8;n++){
            float v0 = acc[n][0], v1 = acc[n][1], v2 = acc[n][2], v3 = acc[n][3];
            if (jt == NTILES-1){
                int jl = jl0 + n*8;
                if (jl   >= CHUNK){ v0 = NEGINF; v2 = NEGINF; }
                if (jl+1 >= CHUNK){ v1 = NEGINF; v3 = NEGINF; }
            }
            s0 += __expf(fmaf(v0, INV_TEMP, -LSE_SHIFT)) + __expf(fmaf(v1, INV_TEMP, -LSE_SHIFT));
            s1 += __expf(fmaf(v2, INV_TEMP, -LSE_SHIFT)) + __expf(fmaf(v3, INV_TEMP, -LSE_SHIFT));
        }
    }

    #pragma unroll
    for (int o=1; o<4; o<<=1){
        s0 += __shfl_xor_sync(FULLMASK, s0, o);
        s1 += __shfl_xor_sync(FULLMASK, s1, o);
    }
    if ((lane & 3) == 0){
        int gq = qOff + qt*128 + w*16 + (lane>>2);
        g_pm[gq*PSTR + split] = LSE_SHIFT;
        g_ps[gq*PSTR + split] = s0;
        g_pm[(gq+8)*PSTR + split] = LSE_SHIFT;
        g_ps[(gq+8)*PSTR + split] = s1;
    }
}

__global__ __launch_bounds__(256) void k_finsc(const int* __restrict__ uids, const int* __restrict__ iids,
                                               const int* __restrict__ pos, const int* __restrict__ neg){
    if (blockIdx.x < 16){
        int q = blockIdx.x*256 + threadIdx.x;
        int T = (q < BQ) ? JT_U : JT_I;
        float M = NEGINF;
        for (int t=0;t<T;t++) M = fmaxf(M, g_pm[q*PSTR+t]);
        float S = 0.f;
        for (int t=0;t<T;t++) S += g_ps[q*PSTR+t]*expf(g_pm[q*PSTR+t]-M);
        float lse = M + logf(S);
        float dmax = fmaxf(lse, LOG_EPS_C);
        float dmin = fminf(lse, LOG_EPS_C);
        float v = dmax + log1pf(expf(dmin - dmax));
        v = warpSum(v);
        __shared__ float sw[8];
        int lane = threadIdx.x & 31, wid = threadIdx.x >> 5;
        if (lane==0) sw[wid]=v;
        __syncthreads();
        if (wid==0){
            float x = lane<8 ? sw[lane] : 0.f;
            x = warpSum(x);
            if (lane==0) atomicAdd(&g_acc[blockIdx.x < 8 ? 1 : 2], x);
        }
    } else {
        int q = (blockIdx.x-16)*8 + (threadIdx.x>>5);
        if (q >= BQ) return;
        int lane = threadIdx.x & 31;
        int u = uids[q], it = iids[q], p = pos[q], ng = neg[q];
        const float* Gu = g_sGu + u*64;
        const float* Eu = g_sEu + u*64;
        const float* Gi = g_sGi + it*64;
        const float* Eit = g_sEi + it*64;
        const float* Ep = g_sEi + p*64;
        const float* En = g_sEi + ng*64;
        float du=0.f, di=0.f, dd=0.f;
        #pragma unroll
        for (int t=0;t<2;t++){
            int rr = lane + 32*t;
            float eu = Eu[rr];
            du += Gu[rr]*eu;
            di += Gi[rr]*Eit[rr];
            dd += eu*(Ep[rr]-En[rr]);
        }
        du = warpSum(du); di = warpSum(di); dd = warpSum(dd);
        if (lane==0){
            atomicAdd(&g_acc[3], du);
            atomicAdd(&g_acc[4], di);
            float x = -dd;
            float sp = fmaxf(x,0.f) + log1pf(expf(-fabsf(x)));
            atomicAdd(&g_acc[5], sp);
        }
    }
}

__global__ void k_out(float* out){
    float Bf = (float)BQ;
    float neg_score = g_acc[1]/Bf + g_acc[2]/Bf;
    float pos_score = (g_acc[3] + g_acc[4]) * INV_TEMP / Bf;
    float loss_s = neg_score - pos_score;
    float loss_r = g_acc[5]/Bf;
    float reg = 1e-7f * g_acc[0];
    out[0] = loss_r + 0.2f*loss_s + reg;
    out[1] = loss_r;
    out[2] = 0.2f*loss_s;
}

// ---------------- launch ----------------
extern "C" void kernel_launch(void* const* d_in, const int* in_sizes, int n_in,
                              void* d_out, int out_size){
    const float* E_u_0    = (const float*)d_in[0];
    const float* E_i_0    = (const float*)d_in[1];
    const float* adj_vals = (const float*)d_in[2];
    const float* W        = (const float*)d_in[3];
    const float* attn_l   = (const float*)d_in[4];
    const float* attn_r   = (const float*)d_in[5];
    const int*   i_idx    = (const int*)d_in[7];
    const int*   uids     = (const int*)d_in[10];
    const int*   iids     = (const int*)d_in[11];
    const int*   pos      = (const int*)d_in[12];
    const int*   neg      = (const int*)d_in[13];
    float* out = (float*)d_out;

    k_init <<<1024, 256>>>(E_u_0, E_i_0);                        // 0
    k_count<<<(NNZc+255)/256, 256>>>(i_idx);                     // 1
    k_feat <<<(NNc+15)/16, 256>>>(0, W, attn_l, attn_r);         // 2
    k_scanA<<<NB_SCAN, 256>>>();                                 // 3
    k_scanC<<<NB_SCAN, 256>>>();                                 // 4
    k_fill <<<(NNZc+255)/256, 256>>>(i_idx);                     // 5
    k_ui   <<<NB_U + NB_I, 256>>>(0, adj_vals, i_idx);           // 6
    k_feat <<<(NNc+15)/16, 256>>>(1, W, attn_l, attn_r);         // 7
    k_ui   <<<NB_U + NB_I, 256>>>(1, adj_vals, i_idx);           // 8
    k_split<<<(NNc*Dc/4 + NQ*Dc/4 + 255)/256, 256>>>(uids, iids);// 9
    k_mma  <<<16*JT_U + 16*JT_I, 256>>>();                       // 10
    k_finsc<<<16 + BQ/8, 256>>>(uids, iids, pos, neg);           // 11
    k_out  <<<1, 1>>>(out);                                      // 12
}

// round 16
// speedup vs baseline: 1.1368x; 1.0252x over previous
#include <cuda_runtime.h>
#include <cuda_bf16.h>
#include <math.h>

#define N_Uc 30000
#define N_Ic 15000
#define NNc  45000
#define Dc   64
#define NNZc 480000
#define BQ   2048
#define NQ   (2*BQ)
#define JT_U 12
#define JT_I 6
#define PSTR 16
#define CHUNK 2500
#define NTILES 40
#define NB_SCAN 59
#define NB_U 3750
#define NB_I 1875
#define INV_TEMP 5.0f
#define LSE_SHIFT 40.0f
#define NEG_SLOPE_C 0.2f
#define LOG_EPS_C (-18.420680743952367f)
#define FULLMASK 0xffffffffu
#define NEGINF (-INFINITY)

typedef unsigned long long ull;
typedef unsigned int uint;
typedef unsigned short ushort;

// ---------------- scratch ----------------
__device__ float g_EuA[N_Uc*Dc], g_EuB[N_Uc*Dc];
__device__ float g_EiA[N_Ic*Dc], g_EiB[N_Ic*Dc];
__device__ float g_sEu[N_Uc*Dc], g_sEi[N_Ic*Dc];
__device__ float g_sGu[N_Uc*Dc], g_sGi[N_Ic*Dc];
__device__ float g_feat[NNc*Dc];
__device__ float g_el[NNc*4], g_er[NNc*4];
__device__ int   g_ioff[N_Ic+1];
__device__ int   g_icur[N_Ic];
__device__ int   g_ilist[NNZc];
__device__ int   g_bsum[64];
__device__ int   g_scancnt;
__device__ float g_pm[NQ*PSTR], g_ps[NQ*PSTR];
__device__ float g_acc[8];
__device__ ushort g_Ehi[NNc*Dc], g_Elo[NNc*Dc];
__device__ ushort g_Qhi[NQ*Dc],  g_Qlo[NQ*Dc];

// ---------------- helpers ----------------
__device__ __forceinline__ float warpSum(float v){
    #pragma unroll
    for (int o=16;o;o>>=1) v += __shfl_xor_sync(FULLMASK, v, o);
    return v;
}
__device__ __forceinline__ int warpSumI(int v){
    #pragma unroll
    for (int o=16;o;o>>=1) v += __shfl_xor_sync(FULLMASK, v, o);
    return v;
}
__device__ __forceinline__ float leakyf(float x){ return x > 0.f ? x : NEG_SLOPE_C*x; }
__device__ __forceinline__ float eluf(float x){ return x > 0.f ? x : expm1f(x); }

struct F4 { float x,y,z,w; };
__device__ __forceinline__ F4 ldf4(const float* p){ float4 v = *(const float4*)p; return {v.x,v.y,v.z,v.w}; }
__device__ __forceinline__ F4 leaky4(F4 a){ return { leakyf(a.x), leakyf(a.y), leakyf(a.z), leakyf(a.w) }; }
__device__ __forceinline__ F4 add4(F4 a, F4 b){ return { a.x+b.x, a.y+b.y, a.z+b.z, a.w+b.w }; }
__device__ __forceinline__ F4 exp4(F4 a){ return { __expf(a.x), __expf(a.y), __expf(a.z), __expf(a.w) }; }
__device__ __forceinline__ F4 warpSum4(F4 v){
    v.x = warpSum(v.x); v.y = warpSum(v.y); v.z = warpSum(v.z); v.w = warpSum(v.w);
    return v;
}
__device__ __forceinline__ float comp4(F4 v, int h){
    return h==0 ? v.x : (h==1 ? v.y : (h==2 ? v.z : v.w));
}
__device__ __forceinline__ unsigned smem_u32(const void* p){
    return (unsigned)__cvta_generic_to_shared(p);
}

#define LDSM4(r0,r1,r2,r3,addr) \
    asm volatile("ldmatrix.sync.aligned.m8n8.x4.shared.b16 {%0,%1,%2,%3}, [%4];" \
        : "=r"(r0),"=r"(r1),"=r"(r2),"=r"(r3) : "r"(addr))

#define MMA16816(c,a0,a1,a2,a3,b0,b1) \
    asm volatile("mma.sync.aligned.m16n8k16.row.col.f32.bf16.bf16.f32 " \
        "{%0,%1,%2,%3}, {%4,%5,%6,%7}, {%8,%9}, {%0,%1,%2,%3};" \
        : "+f"(c[0]),"+f"(c[1]),"+f"(c[2]),"+f"(c[3]) \
        : "r"(a0),"r"(a1),"r"(a2),"r"(a3), "r"(b0),"r"(b1))

// ---------------- setup ----------------
__global__ __launch_bounds__(256) void k_init(const float* __restrict__ E0u, const float* __restrict__ E0i){
    const int TOT = N_Uc*Dc + N_Ic*Dc;
    int gid = blockIdx.x*256 + threadIdx.x;
    if (gid <= N_Ic) g_ioff[gid] = 0;
    if (gid < 8)     g_acc[gid]  = 0.f;
    if (gid == 0)    g_scancnt   = 0;
    float loc = 0.f;
    for (int i = gid; i < TOT; i += gridDim.x*256){
        float v;
        if (i < N_Uc*Dc){ v = E0u[i]; g_EuA[i]=v; g_sEu[i]=v; g_sGu[i]=v; }
        else            { int j=i-N_Uc*Dc; v = E0i[j]; g_EiA[j]=v; g_sEi[j]=v; g_sGi[j]=v; }
        loc += v*v;
    }
    loc = warpSum(loc);
    __shared__ float sw[8];
    int lane = threadIdx.x & 31, wid = threadIdx.x >> 5;
    if (lane==0) sw[wid]=loc;
    __syncthreads();
    if (wid==0){
        float v = lane<8 ? sw[lane] : 0.f;
        v = warpSum(v);
        if (lane==0) atomicAdd(&g_acc[0], v);
    }
}

__global__ __launch_bounds__(256) void k_count(const int* __restrict__ i_idx){
    int j = blockIdx.x*256 + threadIdx.x;
    if (j < NNZc) atomicAdd(&g_ioff[i_idx[j]], 1);
}

// fused scanA + scanC: block-local scan, publish block sums, grid-spin, apply prefix
__global__ __launch_bounds__(256) void k_scanAC(){
    int b = blockIdx.x;
    int i = b*256 + threadIdx.x;
    int cnt = (i < N_Ic) ? g_ioff[i] : 0;
    int lane = threadIdx.x & 31, w = threadIdx.x >> 5;
    int x = cnt;
    #pragma unroll
    for (int o=1;o<32;o<<=1){
        int y = __shfl_up_sync(FULLMASK, x, o);
        if (lane >= o) x += y;
    }
    __shared__ int ws[8];
    __shared__ int spref;
    if (lane==31) ws[w] = x;
    __syncthreads();
    if (w==0){
        int v = lane<8 ? ws[lane] : 0;
        #pragma unroll
        for (int o=1;o<8;o<<=1){
            int y = __shfl_up_sync(FULLMASK, v, o);
            if (lane >= o) v += y;
        }
        if (lane<8) ws[lane] = v;
    }
    __syncthreads();
    int excl = x - cnt + (w>0 ? ws[w-1] : 0);
    if (threadIdx.x == 255){
        g_bsum[b] = excl + cnt;
        __threadfence();
        atomicAdd(&g_scancnt, 1);
    }
    // spin until all blocks have published (all 59 blocks are co-resident)
    if (threadIdx.x == 0){
        while (atomicAdd(&g_scancnt, 0) < NB_SCAN) { }
        __threadfence();
    }
    __syncthreads();
    // inter-block exclusive prefix over bsum[0..b)
    if (threadIdx.x < 32){
        int l = threadIdx.x;
        int i0 = 2*l, i1 = 2*l+1;
        int v0 = (i0 < NB_SCAN && i0 < b) ? g_bsum[i0] : 0;
        int v1 = (i1 < NB_SCAN && i1 < b) ? g_bsum[i1] : 0;
        int s = warpSumI(v0 + v1);
        if (l==0) spref = s;
    }
    __syncthreads();
    if (i < N_Ic){
        int v = excl + spref;
        g_ioff[i] = v; g_icur[i] = v;
    }
    if (i == 0) g_ioff[N_Ic] = NNZc;
}

__global__ __launch_bounds__(256) void k_fill(const int* __restrict__ i_idx){
    int j = blockIdx.x*256 + threadIdx.x;
    if (j < NNZc){
        int p = atomicAdd(&g_icur[i_idx[j]], 1);
        g_ilist[p] = j;
    }
}

// ---------------- per-layer ----------------
// feat = E @ W, 32 rows per block, 8 outputs/thread
__global__ __launch_bounds__(256) void k_feat(int flip, const float* __restrict__ W,
                                              const float* __restrict__ al, const float* __restrict__ ar){
    __shared__ float sW[64*64];
    __shared__ float sh[32*64];
    int tid = threadIdx.x;
    const float* Eu = flip ? g_EuB : g_EuA;
    const float* Ei = flip ? g_EiB : g_EiA;
    int r0 = blockIdx.x*32;
    for (int i=tid;i<4096;i+=256) sW[i]=W[i];
    for (int i=tid;i<2048;i+=256){
        int node = r0 + (i>>6); int k = i&63;
        float v = 0.f;
        if (node < NNc) v = node < N_Uc ? Eu[node*64+k] : Ei[(node-N_Uc)*64+k];
        sh[i] = v;
    }
    __syncthreads();
    int r = tid>>6, c = tid&63;
    float acc[8];
    #pragma unroll
    for (int j=0;j<8;j++) acc[j]=0.f;
    #pragma unroll
    for (int k=0;k<64;k++){
        float wv = sW[k*64+c];
        #pragma unroll
        for (int j=0;j<8;j++) acc[j] += sh[(r+4*j)*64+k]*wv;
    }
    float alc = al[c], arc = ar[c];
    #pragma unroll
    for (int rr=0; rr<8; rr++){
        int node = r0 + r + rr*4;
        if (node < NNc){
            float a = acc[rr];
            g_feat[node*64+c] = a;
            float vl = a*alc, vr = a*arc;
            #pragma unroll
            for (int o=8;o;o>>=1){
                vl += __shfl_down_sync(FULLMASK, vl, o, 16);
                vr += __shfl_down_sync(FULLMASK, vr, o, 16);
            }
            if ((c&15)==0){ g_el[node*4+(c>>4)] = vl; g_er[node*4+(c>>4)] = vr; }
        }
    }
}

// fused user+item GAT/LightGCN kernel: blocks [0,NB_U) user, [NB_U,NB_U+NB_I) item
__global__ __launch_bounds__(256) void k_ui(int flip, const float* __restrict__ vals,
                                            const int* __restrict__ i_idx){
    __shared__ int    s_u[8][32];
    __shared__ float4 s_a4[8][32];
    __shared__ float  s_v[8][32];
    int lane = threadIdx.x & 31;
    int w = threadIdx.x >> 5;
    const float* Eu = flip ? g_EuB : g_EuA;
    const float* Ei = flip ? g_EiB : g_EiA;
    int h = lane >> 3;

    if (blockIdx.x < NB_U){
        // ---------------- user ----------------
        int u = blockIdx.x*8 + w;
        float* EuN = flip ? g_EuA : g_EuB;
        F4 er4 = ldf4(g_er + u*4);
        int src = u;
        if (lane < 16){ src = N_Uc + i_idx[u*16 + lane]; s_v[w][lane] = vals[u*16 + lane]; }
        bool valid = lane < 17;
        F4 a4 = { 0.f,0.f,0.f,0.f };
        if (valid){
            F4 e4 = leaky4(add4(ldf4(g_el + src*4), er4));
            a4 = exp4(e4);
        }
        F4 s4 = warpSum4(a4);
        if (valid){ s_u[w][lane]=src; s_a4[w][lane]=make_float4(a4.x,a4.y,a4.z,a4.w); }
        __syncwarp();
        float g0=0.f, g1=0.f, z0=0.f, z1=0.f;
        #pragma unroll
        for (int k=0;k<16;k++){
            int sk = s_u[w][k];
            float a = ((const float*)&s_a4[w][k])[h];
            float vv = s_v[w][k];
            float2 f2 = ((const float2*)(g_feat + sk*64))[lane];
            float2 i2 = ((const float2*)(Ei + (sk-N_Uc)*64))[lane];
            g0 += a*f2.x;  g1 += a*f2.y;
            z0 += vv*i2.x; z1 += vv*i2.y;
        }
        {
            float a = ((const float*)&s_a4[w][16])[h];
            float2 f2 = ((const float2*)(g_feat + u*64))[lane];
            g0 += a*f2.x; g1 += a*f2.y;
        }
        float sh = comp4(s4, h);
        float2* sg = (float2*)(g_sGu + u*64);
        float2 cg = sg[lane]; cg.x += eluf(g0/sh); cg.y += eluf(g1/sh); sg[lane] = cg;
        float2 eu = ((const float2*)(Eu + u*64))[lane];
        float2 e; e.x = eu.x + z0; e.y = eu.y + z1;
        ((float2*)(EuN + u*64))[lane] = e;
        float2* se = (float2*)(g_sEu + u*64);
        float2 cs = se[lane]; cs.x += e.x; cs.y += e.y; se[lane] = cs;
    } else {
        // ---------------- item ----------------
        int i = (blockIdx.x - NB_U)*8 + w;
        if (i >= N_Ic) return;
        int node = N_Uc + i;
        float* EiN = flip ? g_EiA : g_EiB;
        int off = g_ioff[i];
        int cnt = g_ioff[i+1] - off;
        int deg = cnt + 1;
        F4 er4 = ldf4(g_er + node*4);
        float g0=0.f, g1=0.f, z0=0.f, z1=0.f;
        F4 ssum = {0.f,0.f,0.f,0.f};
        for (int base=0; base<deg; base+=32){
            int k = base + lane;
            if (k < deg){
                int src; float vv;
                if (k < cnt){
                    int j = g_ilist[off+k];
                    src = j >> 4; vv = vals[j];
                } else { src = node; vv = 0.f; }
                F4 e4 = leaky4(add4(ldf4(g_el + src*4), er4));
                F4 a4 = exp4(e4);
                ssum = add4(ssum, a4);
                s_u[w][lane] = src;
                s_a4[w][lane] = make_float4(a4.x, a4.y, a4.z, a4.w);
                s_v[w][lane] = vv;
            }
            __syncwarp();
            int kmax = min(32, deg - base);
            for (int kk=0; kk<kmax; kk++){
                int sk = s_u[w][kk];
                float a = ((const float*)&s_a4[w][kk])[h];
                float2 f2 = ((const float2*)(g_feat + sk*64))[lane];
                g0 += a*f2.x; g1 += a*f2.y;
                if (sk < N_Uc){
                    float vv = s_v[w][kk];
                    float2 u2 = ((const float2*)(Eu + sk*64))[lane];
                    z0 += vv*u2.x; z1 += vv*u2.y;
                }
            }
            __syncwarp();
        }
        F4 s4 = warpSum4(ssum);
        float sh = comp4(s4, h);
        float2* sg = (float2*)(g_sGi + i*64);
        float2 cg = sg[lane]; cg.x += eluf(g0/sh); cg.y += eluf(g1/sh); sg[lane] = cg;
        float2 ei = ((const float2*)(Ei + i*64))[lane];
        float2 e; e.x = ei.x + z0; e.y = ei.y + z1;
        ((float2*)(EiN + i*64))[lane] = e;
        float2* se = (float2*)(g_sEi + i*64);
        float2 cs = se[lane]; cs.x += e.x; cs.y += e.y; se[lane] = cs;
    }
}

// ---------------- bf16 split (fused E + Q) ----------------
__global__ __launch_bounds__(256) void k_split(const int* __restrict__ uids, const int* __restrict__ iids){
    const int NE = NNc*Dc/4;
    const int NQ4 = NQ*Dc/4;
    int t = blockIdx.x*256 + threadIdx.x;
    const float* src;
    ushort *dhi, *dlo;
    int idx;
    if (t < NE){
        idx = t*4;
        int row = idx >> 6, k = idx & 63;
        src = ((row < N_Uc) ? (g_sEu + row*64) : (g_sEi + (row-N_Uc)*64)) + k;
        dhi = g_Ehi + idx; dlo = g_Elo + idx;
    } else {
        int t2 = t - NE;
        if (t2 >= NQ4) return;
        idx = t2*4;
        int q = idx >> 6, k = idx & 63;
        src = ((q < BQ) ? (g_sGu + uids[q]*64) : (g_sGi + iids[q-BQ]*64)) + k;
        dhi = g_Qhi + idx; dlo = g_Qlo + idx;
    }
    float4 v = *(const float4*)src;
    float vv[4] = {v.x, v.y, v.z, v.w};
    uint h2[2], l2[2];
    #pragma unroll
    for (int p=0;p<2;p++){
        __nv_bfloat16 h0 = __float2bfloat16_rn(vv[2*p]);
        __nv_bfloat16 h1 = __float2bfloat16_rn(vv[2*p+1]);
        __nv_bfloat16 l0 = __float2bfloat16_rn(vv[2*p]   - __bfloat162float(h0));
        __nv_bfloat16 l1 = __float2bfloat16_rn(vv[2*p+1] - __bfloat162float(h1));
        h2[p] = (uint)__bfloat16_as_ushort(h0) | ((uint)__bfloat16_as_ushort(h1) << 16);
        l2[p] = (uint)__bfloat16_as_ushort(l0) | ((uint)__bfloat16_as_ushort(l1) << 16);
    }
    *(uint2*)dhi = make_uint2(h2[0], h2[1]);
    *(uint2*)dlo = make_uint2(l2[0], l2[1]);
}

// ---------------- loss: bf16 split MMA + fixed-shift LSE ----------------
__global__ __launch_bounds__(256,2) void k_mma(){
    __shared__ uint sEhi[64*36];
    __shared__ uint sElo[64*36];
    int bx = blockIdx.x;
    int tid = threadIdx.x;
    int lane = tid & 31, w = tid >> 5;
    int qt, split, qOff, eOff;
    if (bx < 16*JT_U){ qt = bx / JT_U; split = bx % JT_U; qOff = 0;    eOff = 0; }
    else { int b = bx - 16*JT_U; qt = b / JT_I; split = b % JT_I; qOff = BQ; eOff = N_Uc; }
    int rowBase = eOff + split*CHUNK;
    int rowEnd  = rowBase + CHUNK;

    int qrow = qOff + qt*128 + w*16 + (lane>>2);
    const uint* Qh = (const uint*)g_Qhi;
    const uint* Ql = (const uint*)g_Qlo;
    uint Ahi[4][4], Alo[4][4];
    #pragma unroll
    for (int ks=0; ks<4; ks++){
        int k2 = ks*8 + (lane&3);
        Ahi[ks][0] = Qh[ qrow   *32 + k2    ];
        Ahi[ks][1] = Qh[(qrow+8)*32 + k2    ];
        Ahi[ks][2] = Qh[ qrow   *32 + k2 + 4];
        Ahi[ks][3] = Qh[(qrow+8)*32 + k2 + 4];
        Alo[ks][0] = Ql[ qrow   *32 + k2    ];
        Alo[ks][1] = Ql[(qrow+8)*32 + k2    ];
        Alo[ks][2] = Ql[ qrow   *32 + k2 + 4];
        Alo[ks][3] = Ql[(qrow+8)*32 + k2 + 4];
    }

    int L8 = lane & 7, g = lane >> 3;
    int j_off = ((g & 2) << 2) + L8;
    int k_off2 = (g & 1) * 16;
    uint laneB = (uint)(j_off*144 + k_off2);
    uint baseHi = smem_u32(sEhi) + laneB;
    uint baseLo = smem_u32(sElo) + laneB;

    int rr = tid >> 2, cc = tid & 3;
    const uint4* Eh4 = (const uint4*)g_Ehi;
    const uint4* El4 = (const uint4*)g_Elo;
    uint4 rp0, rp1, rp2, rp3;
    {
        int jj = rowBase + rr;
        bool v = jj < rowEnd;
        long gi = (long)jj*8 + cc*2;
        rp0 = v ? Eh4[gi]   : make_uint4(0,0,0,0);
        rp1 = v ? Eh4[gi+1] : make_uint4(0,0,0,0);
        rp2 = v ? El4[gi]   : make_uint4(0,0,0,0);
        rp3 = v ? El4[gi+1] : make_uint4(0,0,0,0);
    }

    float s0 = 0.f, s1 = 0.f;

    for (int jt=0; jt<NTILES; jt++){
        __syncthreads();
        {
            uint so = rr*36 + cc*8;
            *(uint4*)(sEhi + so)     = rp0;
            *(uint4*)(sEhi + so + 4) = rp1;
            *(uint4*)(sElo + so)     = rp2;
            *(uint4*)(sElo + so + 4) = rp3;
        }
        __syncthreads();
        if (jt+1 < NTILES){
            int jj = rowBase + (jt+1)*64 + rr;
            bool v = jj < rowEnd;
            long gi = (long)jj*8 + cc*2;
            rp0 = v ? Eh4[gi]   : make_uint4(0,0,0,0);
            rp1 = v ? Eh4[gi+1] : make_uint4(0,0,0,0);
            rp2 = v ? El4[gi]   : make_uint4(0,0,0,0);
            rp3 = v ? El4[gi+1] : make_uint4(0,0,0,0);
        }

        float acc[8][4];
        #pragma unroll
        for (int n=0;n<8;n++){ acc[n][0]=0.f; acc[n][1]=0.f; acc[n][2]=0.f; acc[n][3]=0.f; }

        #pragma unroll
        for (int ks=0; ks<4; ks++){
            uint kb = ks*32;
            #pragma unroll
            for (int p=0; p<4; p++){
                uint bh0,bh1,bh2,bh3, bl0,bl1,bl2,bl3;
                LDSM4(bh0,bh1,bh2,bh3, baseHi + p*2304 + kb);
                LDSM4(bl0,bl1,bl2,bl3, baseLo + p*2304 + kb);
                MMA16816(acc[2*p],   Ahi[ks][0],Ahi[ks][1],Ahi[ks][2],Ahi[ks][3], bh0,bh1);
                MMA16816(acc[2*p],   Alo[ks][0],Alo[ks][1],Alo[ks][2],Alo[ks][3], bh0,bh1);
                MMA16816(acc[2*p],   Ahi[ks][0],Ahi[ks][1],Ahi[ks][2],Ahi[ks][3], bl0,bl1);
                MMA16816(acc[2*p+1], Ahi[ks][0],Ahi[ks][1],Ahi[ks][2],Ahi[ks][3], bh2,bh3);
                MMA16816(acc[2*p+1], Alo[ks][0],Alo[ks][1],Alo[ks][2],Alo[ks][3], bh2,bh3);
                MMA16816(acc[2*p+1], Ahi[ks][0],Ahi[ks][1],Ahi[ks][2],Ahi[ks][3], bl2,bl3);
            }
        }

        int jl0 = jt*64 + 2*(lane&3);
        #pragma unroll
        for (int n=0;n<8;n++){
            float v0 = acc[n][0], v1 = acc[n][1], v2 = acc[n][2], v3 = acc[n][3];
            if (jt == NTILES-1){
                int jl = jl0 + n*8;
                if (jl   >= CHUNK){ v0 = NEGINF; v2 = NEGINF; }
                if (jl+1 >= CHUNK){ v1 = NEGINF; v3 = NEGINF; }
            }
            s0 += __expf(fmaf(v0, INV_TEMP, -LSE_SHIFT)) + __expf(fmaf(v1, INV_TEMP, -LSE_SHIFT));
            s1 += __expf(fmaf(v2, INV_TEMP, -LSE_SHIFT)) + __expf(fmaf(v3, INV_TEMP, -LSE_SHIFT));
        }
    }

    #pragma unroll
    for (int o=1; o<4; o<<=1){
        s0 += __shfl_xor_sync(FULLMASK, s0, o);
        s1 += __shfl_xor_sync(FULLMASK, s1, o);
    }
    if ((lane & 3) == 0){
        int gq = qOff + qt*128 + w*16 + (lane>>2);
        g_pm[gq*PSTR + split] = LSE_SHIFT;
        g_ps[gq*PSTR + split] = s0;
        g_pm[(gq+8)*PSTR + split] = LSE_SHIFT;
        g_ps[(gq+8)*PSTR + split] = s1;
    }
}

__global__ __launch_bounds__(256) void k_finsc(const int* __restrict__ uids, const int* __restrict__ iids,
                                               const int* __restrict__ pos, const int* __restrict__ neg){
    if (blockIdx.x < 16){
        int q = blockIdx.x*256 + threadIdx.x;
        int T = (q < BQ) ? JT_U : JT_I;
        float M = NEGINF;
        for (int t=0;t<T;t++) M = fmaxf(M, g_pm[q*PSTR+t]);
        float S = 0.f;
        for (int t=0;t<T;t++) S += g_ps[q*PSTR+t]*expf(g_pm[q*PSTR+t]-M);
        float lse = M + logf(S);
        float dmax = fmaxf(lse, LOG_EPS_C);
        float dmin = fminf(lse, LOG_EPS_C);
        float v = dmax + log1pf(expf(dmin - dmax));
        v = warpSum(v);
        __shared__ float sw[8];
        int lane = threadIdx.x & 31, wid = threadIdx.x >> 5;
        if (lane==0) sw[wid]=v;
        __syncthreads();
        if (wid==0){
            float x = lane<8 ? sw[lane] : 0.f;
            x = warpSum(x);
            if (lane==0) atomicAdd(&g_acc[blockIdx.x < 8 ? 1 : 2], x);
        }
    } else {
        int q = (blockIdx.x-16)*8 + (threadIdx.x>>5);
        if (q >= BQ) return;
        int lane = threadIdx.x & 31;
        int u = uids[q], it = iids[q], p = pos[q], ng = neg[q];
        const float* Gu = g_sGu + u*64;
        const float* Eu = g_sEu + u*64;
        const float* Gi = g_sGi + it*64;
        const float* Eit = g_sEi + it*64;
        const float* Ep = g_sEi + p*64;
        const float* En = g_sEi + ng*64;
        float du=0.f, di=0.f, dd=0.f;
        #pragma unroll
        for (int t=0;t<2;t++){
            int rr = lane + 32*t;
            float eu = Eu[rr];
            du += Gu[rr]*eu;
            di += Gi[rr]*Eit[rr];
            dd += eu*(Ep[rr]-En[rr]);
        }
        du = warpSum(du); di = warpSum(di); dd = warpSum(dd);
        if (lane==0){
            atomicAdd(&g_acc[3], du);
            atomicAdd(&g_acc[4], di);
            float x = -dd;
            float sp = fmaxf(x,0.f) + log1pf(expf(-fabsf(x)));
            atomicAdd(&g_acc[5], sp);
        }
    }
}

__global__ void k_out(float* out){
    float Bf = (float)BQ;
    float neg_score = g_acc[1]/Bf + g_acc[2]/Bf;
    float pos_score = (g_acc[3] + g_acc[4]) * INV_TEMP / Bf;
    float loss_s = neg_score - pos_score;
    float loss_r = g_acc[5]/Bf;
    float reg = 1e-7f * g_acc[0];
    out[0] = loss_r + 0.2f*loss_s + reg;
    out[1] = loss_r;
    out[2] = 0.2f*loss_s;
}

// ---------------- launch ----------------
extern "C" void kernel_launch(void* const* d_in, const int* in_sizes, int n_in,
                              void* d_out, int out_size){
    const float* E_u_0    = (const float*)d_in[0];
    const float* E_i_0    = (const float*)d_in[1];
    const float* adj_vals = (const float*)d_in[2];
    const float* W        = (const float*)d_in[3];
    const float* attn_l   = (const float*)d_in[4];
    const float* attn_r   = (const float*)d_in[5];
    const int*   i_idx    = (const int*)d_in[7];
    const int*   uids     = (const int*)d_in[10];
    const int*   iids     = (const int*)d_in[11];
    const int*   pos      = (const int*)d_in[12];
    const int*   neg      = (const int*)d_in[13];
    float* out = (float*)d_out;

    k_init  <<<1024, 256>>>(E_u_0, E_i_0);                        // 0
    k_count <<<(NNZc+255)/256, 256>>>(i_idx);                     // 1
    k_feat  <<<(NNc+31)/32, 256>>>(0, W, attn_l, attn_r);         // 2
    k_scanAC<<<NB_SCAN, 256>>>();                                 // 3
    k_fill  <<<(NNZc+255)/256, 256>>>(i_idx);                     // 4
    k_ui    <<<NB_U + NB_I, 256>>>(0, adj_vals, i_idx);           // 5
    k_feat  <<<(NNc+31)/32, 256>>>(1, W, attn_l, attn_r);         // 6
    k_ui    <<<NB_U + NB_I, 256>>>(1, adj_vals, i_idx);           // 7
    k_split <<<(NNc*Dc/4 + NQ*Dc/4 + 255)/256, 256>>>(uids, iids);// 8
    k_mma   <<<16*JT_U + 16*JT_I, 256>>>();                       // 9
    k_finsc <<<16 + BQ/8, 256>>>(uids, iids, pos, neg);           // 10
    k_out   <<<1, 1>>>(out);                                      // 11
}